// round 1
// baseline (speedup 1.0000x reference)
#include <cuda_runtime.h>
#include <math.h>

#define EMBED 512
#define HEADS 8
#define HDIM 64
#define SEQL 65
#define NPATCH 64
#define PFEAT 48
#define HID 1024
#define NCLS 10
#define BATCH 2048

// global scratch (no allocations allowed)
__device__ __align__(16) float g_ctpre[BATCH * EMBED];
__device__ __align__(16) float g_ct[BATCH * EMBED];
__device__ __align__(16) float g_h[BATCH * HID];

// ---------------------------------------------------------------------------
// Kernel A: one CTA per batch element.
// patchify -> emb GEMM -> seq(65x512, smem) -> per-head q GEMM -> scores ->
// column-softmax -> att row 0 -> ct_pre (b,512) to global.
// ---------------------------------------------------------------------------
__global__ __launch_bounds__(256, 1) void vit_attn_kernel(
    const float* __restrict__ x, const float* __restrict__ proj_w,
    const float* __restrict__ proj_b, const float* __restrict__ cls,
    const float* __restrict__ pos, const float* __restrict__ wq,
    const float* __restrict__ bq)
{
    extern __shared__ float sm[];
    float* seq = sm;                       // 65*512 = 33280
    float* qh  = seq + SEQL * EMBED;       // 65*66  = 4290
    float* sc  = qh + SEQL * 66;           // 65*66  = 4290
    float* wt  = sc + SEQL * 66;           // 64*66  = 4224 (max tile)
    float* ps  = wt + 64 * 66;             // 64*49  = 3136
    float* ctp = ps + 64 * 49;             // 512
    float* w0s = ctp + EMBED;              // 66

    const int b = blockIdx.x;
    const int t = threadIdx.x;
    const int tx = t & 31, ty = t >> 5;

    // ---- phase 0: extract patches ----
    const float* xb = x + (size_t)b * 3 * 32 * 32;
    for (int idx = t; idx < NPATCH * PFEAT; idx += 256) {
        int n = idx / PFEAT, f = idx % PFEAT;
        int c = f >> 4, r4 = (f >> 2) & 3, c4 = f & 3;
        int py = n >> 3, px = n & 7;
        ps[n * 49 + f] = xb[c * 1024 + (py * 4 + r4) * 32 + (px * 4 + c4)];
    }
    // seq row 0 = cls + pos[0]
    for (int e = t; e < EMBED; e += 256) seq[e] = cls[e] + pos[e];
    __syncthreads();

    // ---- phase 1: emb = p @ proj_w^T + proj_b; seq[1+n] = emb + pos ----
    for (int e0 = 0; e0 < EMBED; e0 += 64) {
        {   // stage proj_w tile [f=48][e=64], stride 66
            int e = t >> 2, fc = (t & 3) * 12;
            const float4* src = (const float4*)(proj_w + (size_t)(e0 + e) * PFEAT + fc);
            #pragma unroll
            for (int j = 0; j < 3; j++) {
                float4 v = src[j];
                wt[(fc + j * 4 + 0) * 66 + e] = v.x;
                wt[(fc + j * 4 + 1) * 66 + e] = v.y;
                wt[(fc + j * 4 + 2) * 66 + e] = v.z;
                wt[(fc + j * 4 + 3) * 66 + e] = v.w;
            }
        }
        __syncthreads();
        int e1 = e0 + 2 * tx;
        float acc[8][2];
        float pb0 = proj_b[e1], pb1 = proj_b[e1 + 1];
        #pragma unroll
        for (int i = 0; i < 8; i++) { acc[i][0] = pb0; acc[i][1] = pb1; }
        #pragma unroll 4
        for (int f = 0; f < PFEAT; f++) {
            float wv0 = wt[f * 66 + 2 * tx], wv1 = wt[f * 66 + 2 * tx + 1];
            #pragma unroll
            for (int i = 0; i < 8; i++) {
                float pv = ps[(ty + 8 * i) * 49 + f];
                acc[i][0] += pv * wv0; acc[i][1] += pv * wv1;
            }
        }
        #pragma unroll
        for (int i = 0; i < 8; i++) {
            int n = ty + 8 * i;
            seq[(1 + n) * EMBED + e1]     = acc[i][0] + pos[(1 + n) * EMBED + e1];
            seq[(1 + n) * EMBED + e1 + 1] = acc[i][1] + pos[(1 + n) * EMBED + e1 + 1];
        }
        __syncthreads();
    }

    const int s8 = (ty == 0) ? 64 : ty;    // 9th row handled by warp 0 only
    const int c2 = (tx == 0) ? 64 : tx;    // 65th column handled by lane 0 only

    // ---- per-head attention ----
    for (int h = 0; h < HEADS; h++) {
        // q GEMM: qh[65][64] = seq @ wq_h^T + bq_h
        float qa[9][2];
        {
            float bq0 = bq[h * HDIM + 2 * tx], bq1 = bq[h * HDIM + 2 * tx + 1];
            #pragma unroll
            for (int i = 0; i < 9; i++) { qa[i][0] = bq0; qa[i][1] = bq1; }
        }
        for (int d0 = 0; d0 < EMBED; d0 += 64) {
            {   // stage wq tile [d'=64][kq=64], stride 66
                int kq = t >> 2, dc = (t & 3) * 16;
                const float4* src = (const float4*)(wq + (size_t)(h * HDIM + kq) * EMBED + d0 + dc);
                #pragma unroll
                for (int j = 0; j < 4; j++) {
                    float4 v = src[j];
                    wt[(dc + j * 4 + 0) * 66 + kq] = v.x;
                    wt[(dc + j * 4 + 1) * 66 + kq] = v.y;
                    wt[(dc + j * 4 + 2) * 66 + kq] = v.z;
                    wt[(dc + j * 4 + 3) * 66 + kq] = v.w;
                }
            }
            __syncthreads();
            #pragma unroll 4
            for (int d = 0; d < 64; d++) {
                float w0 = wt[d * 66 + 2 * tx], w1 = wt[d * 66 + 2 * tx + 1];
                #pragma unroll
                for (int i = 0; i < 8; i++) {
                    float sv = seq[(ty + 8 * i) * EMBED + d0 + d];
                    qa[i][0] += sv * w0; qa[i][1] += sv * w1;
                }
                float sv8 = seq[s8 * EMBED + d0 + d];
                qa[8][0] += sv8 * w0; qa[8][1] += sv8 * w1;
            }
            __syncthreads();
        }
        #pragma unroll
        for (int i = 0; i < 8; i++) {
            qh[(ty + 8 * i) * 66 + 2 * tx]     = qa[i][0];
            qh[(ty + 8 * i) * 66 + 2 * tx + 1] = qa[i][1];
        }
        if (ty == 0) { qh[64 * 66 + 2 * tx] = qa[8][0]; qh[64 * 66 + 2 * tx + 1] = qa[8][1]; }
        __syncthreads();

        // scores[s][t] = (q_s . q_t) / 8
        float sa[9][3];
        #pragma unroll
        for (int i = 0; i < 9; i++) { sa[i][0] = 0.f; sa[i][1] = 0.f; sa[i][2] = 0.f; }
        #pragma unroll 2
        for (int k = 0; k < HDIM; k++) {
            float qt0 = qh[tx * 66 + k];
            float qt1 = qh[(tx + 32) * 66 + k];
            float qt2 = qh[c2 * 66 + k];
            #pragma unroll
            for (int i = 0; i < 8; i++) {
                float qs = qh[(ty + 8 * i) * 66 + k];
                sa[i][0] += qs * qt0; sa[i][1] += qs * qt1; sa[i][2] += qs * qt2;
            }
            float qs8 = qh[s8 * 66 + k];
            sa[8][0] += qs8 * qt0; sa[8][1] += qs8 * qt1; sa[8][2] += qs8 * qt2;
        }
        #pragma unroll
        for (int i = 0; i < 8; i++) {
            int s = ty + 8 * i;
            sc[s * 66 + tx]      = sa[i][0] * 0.125f;
            sc[s * 66 + tx + 32] = sa[i][1] * 0.125f;
            if (tx == 0) sc[s * 66 + 64] = sa[i][2] * 0.125f;
        }
        if (ty == 0) {
            sc[64 * 66 + tx]      = sa[8][0] * 0.125f;
            sc[64 * 66 + tx + 32] = sa[8][1] * 0.125f;
            if (tx == 0) sc[64 * 66 + 64] = sa[8][2] * 0.125f;
        }
        __syncthreads();

        // column softmax (over s), keep only row-0 weights
        if (t < SEQL) {
            float m = -1e30f;
            for (int s = 0; s < SEQL; s++) m = fmaxf(m, sc[s * 66 + t]);
            float Z = 0.f;
            for (int s = 0; s < SEQL; s++) Z += expf(sc[s * 66 + t] - m);
            w0s[t] = expf(sc[t] - m) / Z;   // sc[0*66 + t]
        }
        __syncthreads();

        // att0[k] = sum_t w0[t] * q[t][k]
        if (t < HDIM) {
            float a = 0.f;
            for (int tt = 0; tt < SEQL; tt++) a += w0s[tt] * qh[tt * 66 + t];
            ctp[h * HDIM + t] = a;
        }
        __syncthreads();
    }

    for (int e = t; e < EMBED; e += 256) g_ctpre[(size_t)b * EMBED + e] = ctp[e];
}

// ---------------------------------------------------------------------------
// Generic batched GEMM: C[M,N] = A[M,K] @ W[N,K]^T + bias, optional exact GELU
// block tile 64x64, 256 threads, 4x4 per thread, K staged in 32-chunks
// ---------------------------------------------------------------------------
__global__ __launch_bounds__(256, 2) void gemm_bias_kernel(
    const float* __restrict__ A, const float* __restrict__ W,
    const float* __restrict__ bias, float* __restrict__ C,
    int M, int N, int K, int act)
{
    __shared__ __align__(16) float As[32][68];
    __shared__ __align__(16) float Ws[32][68];
    const int m0 = blockIdx.y * 64, n0 = blockIdx.x * 64;
    const int t = threadIdx.x;
    const int tn = t & 15, tm = t >> 4;
    float acc[4][4] = {};

    for (int k0 = 0; k0 < K; k0 += 32) {
        #pragma unroll
        for (int l = 0; l < 2; l++) {
            int i = t + l * 256;         // 512 float4 loads total
            int row = i >> 3;
            int kk = (i & 7) * 4;
            float4 v = *(const float4*)(A + (size_t)(m0 + row) * K + k0 + kk);
            As[kk + 0][row] = v.x; As[kk + 1][row] = v.y;
            As[kk + 2][row] = v.z; As[kk + 3][row] = v.w;
            float4 u = *(const float4*)(W + (size_t)(n0 + row) * K + k0 + kk);
            Ws[kk + 0][row] = u.x; Ws[kk + 1][row] = u.y;
            Ws[kk + 2][row] = u.z; Ws[kk + 3][row] = u.w;
        }
        __syncthreads();
        #pragma unroll
        for (int k = 0; k < 32; k++) {
            float4 av = *(const float4*)&As[k][tm * 4];
            float4 wv = *(const float4*)&Ws[k][tn * 4];
            acc[0][0] += av.x * wv.x; acc[0][1] += av.x * wv.y; acc[0][2] += av.x * wv.z; acc[0][3] += av.x * wv.w;
            acc[1][0] += av.y * wv.x; acc[1][1] += av.y * wv.y; acc[1][2] += av.y * wv.z; acc[1][3] += av.y * wv.w;
            acc[2][0] += av.z * wv.x; acc[2][1] += av.z * wv.y; acc[2][2] += av.z * wv.z; acc[2][3] += av.z * wv.w;
            acc[3][0] += av.w * wv.x; acc[3][1] += av.w * wv.y; acc[3][2] += av.w * wv.z; acc[3][3] += av.w * wv.w;
        }
        __syncthreads();
    }
    #pragma unroll
    for (int i = 0; i < 4; i++) {
        #pragma unroll
        for (int j = 0; j < 4; j++) {
            int m = m0 + tm * 4 + i, n = n0 + tn * 4 + j;
            float v = acc[i][j] + bias[n];
            if (act) v = 0.5f * v * (1.f + erff(v * 0.70710678118654752f));
            C[(size_t)m * N + n] = v;
        }
    }
}

// logits: one CTA per batch row, one warp per class
__global__ __launch_bounds__(320) void logits_kernel(
    const float* __restrict__ h, const float* __restrict__ w2,
    const float* __restrict__ b2, float* __restrict__ out)
{
    int b = blockIdx.x;
    int lane = threadIdx.x & 31, w = threadIdx.x >> 5;  // 10 warps
    const float* hb = h + (size_t)b * HID;
    float a = 0.f;
    for (int k = lane; k < HID; k += 32) a += hb[k] * w2[(size_t)w * HID + k];
    #pragma unroll
    for (int o = 16; o > 0; o >>= 1) a += __shfl_xor_sync(0xffffffffu, a, o);
    if (lane == 0) out[(size_t)b * NCLS + w] = a + b2[w];
}

extern "C" void kernel_launch(void* const* d_in, const int* in_sizes, int n_in,
                              void* d_out, int out_size)
{
    const float* x      = (const float*)d_in[0];
    const float* proj_w = (const float*)d_in[1];
    const float* proj_b = (const float*)d_in[2];
    const float* cls    = (const float*)d_in[3];
    const float* pos    = (const float*)d_in[4];
    const float* wq     = (const float*)d_in[5];
    const float* bq     = (const float*)d_in[6];
    const float* wo     = (const float*)d_in[7];
    const float* bo     = (const float*)d_in[8];
    const float* w1     = (const float*)d_in[9];
    const float* b1     = (const float*)d_in[10];
    const float* w2     = (const float*)d_in[11];
    const float* b2     = (const float*)d_in[12];
    float* out = (float*)d_out;

    float *p_ctpre, *p_ct, *p_h;
    cudaGetSymbolAddress((void**)&p_ctpre, g_ctpre);
    cudaGetSymbolAddress((void**)&p_ct, g_ct);
    cudaGetSymbolAddress((void**)&p_h, g_h);

    const size_t smemA = (size_t)(SEQL * EMBED + 2 * SEQL * 66 + 64 * 66 +
                                  64 * 49 + EMBED + 66) * sizeof(float);
    cudaFuncSetAttribute(vit_attn_kernel,
                         cudaFuncAttributeMaxDynamicSharedMemorySize, (int)smemA);

    vit_attn_kernel<<<BATCH, 256, smemA>>>(x, proj_w, proj_b, cls, pos, wq, bq);
    gemm_bias_kernel<<<dim3(EMBED / 64, BATCH / 64), 256>>>(
        p_ctpre, wo, bo, p_ct, BATCH, EMBED, EMBED, 0);
    gemm_bias_kernel<<<dim3(HID / 64, BATCH / 64), 256>>>(
        p_ct, w1, b1, p_h, BATCH, HID, EMBED, 1);
    logits_kernel<<<BATCH, 320>>>(p_h, w2, b2, out);
}

// round 2
// speedup vs baseline: 2.2672x; 2.2672x over previous
#include <cuda_runtime.h>
#include <math.h>

#define EMBED 512
#define HEADS 8
#define HDIM 64
#define SEQL 65
#define NPATCH 64
#define PFEAT 48
#define HID 1024
#define NCLS 10
#define BATCH 2048
#define MTOT (BATCH * SEQL)   // 133120

// global scratch (no allocations allowed)
__device__ __align__(16) float g_seq[(size_t)MTOT * EMBED];
__device__ __align__(16) float g_q[(size_t)MTOT * EMBED];
__device__ __align__(16) float g_ctpre[BATCH * EMBED];
__device__ __align__(16) float g_ct[BATCH * EMBED];
__device__ __align__(16) float g_h[BATCH * HID];

// ---- f32x2 packed-FMA helpers (SASS FFMA2, PTX-only path) ----
__device__ __forceinline__ void ffma2(unsigned long long& d,
                                      unsigned long long a,
                                      unsigned long long b) {
    asm("fma.rn.f32x2 %0, %1, %2, %0;" : "+l"(d) : "l"(a), "l"(b));
}
__device__ __forceinline__ unsigned long long packdup(float x) {
    unsigned long long r;
    asm("mov.b64 %0, {%1, %2};" : "=l"(r) : "f"(x), "f"(x));
    return r;
}
__device__ __forceinline__ float2 unpack2(unsigned long long v) {
    float2 r;
    asm("mov.b64 {%0, %1}, %2;" : "=f"(r.x), "=f"(r.y) : "l"(v));
    return r;
}

// ---------------------------------------------------------------------------
// K1: one CTA per batch element: patchify -> emb GEMM -> +pos -> g_seq
// ---------------------------------------------------------------------------
__global__ __launch_bounds__(256) void seq_kernel(
    const float* __restrict__ x, const float* __restrict__ proj_w,
    const float* __restrict__ proj_b, const float* __restrict__ cls,
    const float* __restrict__ pos, float* __restrict__ seqo)
{
    __shared__ float ps[NPATCH * 49];
    __shared__ float wt[PFEAT * 66];

    const int b = blockIdx.x;
    const int t = threadIdx.x;
    const int tx = t & 31, ty = t >> 5;
    float* sb = seqo + (size_t)b * SEQL * EMBED;

    // patches
    const float* xb = x + (size_t)b * 3 * 32 * 32;
    for (int idx = t; idx < NPATCH * PFEAT; idx += 256) {
        int n = idx / PFEAT, f = idx % PFEAT;
        int c = f >> 4, r4 = (f >> 2) & 3, c4 = f & 3;
        int py = n >> 3, px = n & 7;
        ps[n * 49 + f] = xb[c * 1024 + (py * 4 + r4) * 32 + (px * 4 + c4)];
    }
    // row 0 = cls + pos[0]
    for (int e = t; e < EMBED; e += 256) sb[e] = cls[e] + pos[e];
    __syncthreads();

    for (int e0 = 0; e0 < EMBED; e0 += 64) {
        {   // stage proj_w tile [f=48][e=64], stride 66
            int e = t >> 2, fc = (t & 3) * 12;
            const float4* src = (const float4*)(proj_w + (size_t)(e0 + e) * PFEAT + fc);
            #pragma unroll
            for (int j = 0; j < 3; j++) {
                float4 v = src[j];
                wt[(fc + j * 4 + 0) * 66 + e] = v.x;
                wt[(fc + j * 4 + 1) * 66 + e] = v.y;
                wt[(fc + j * 4 + 2) * 66 + e] = v.z;
                wt[(fc + j * 4 + 3) * 66 + e] = v.w;
            }
        }
        __syncthreads();
        int e1 = e0 + 2 * tx;
        float acc[8][2];
        float pb0 = proj_b[e1], pb1 = proj_b[e1 + 1];
        #pragma unroll
        for (int i = 0; i < 8; i++) { acc[i][0] = pb0; acc[i][1] = pb1; }
        #pragma unroll 4
        for (int f = 0; f < PFEAT; f++) {
            float wv0 = wt[f * 66 + 2 * tx], wv1 = wt[f * 66 + 2 * tx + 1];
            #pragma unroll
            for (int i = 0; i < 8; i++) {
                float pv = ps[(ty + 8 * i) * 49 + f];
                acc[i][0] += pv * wv0; acc[i][1] += pv * wv1;
            }
        }
        #pragma unroll
        for (int i = 0; i < 8; i++) {
            int n = ty + 8 * i;
            sb[(1 + n) * EMBED + e1]     = acc[i][0] + pos[(1 + n) * EMBED + e1];
            sb[(1 + n) * EMBED + e1 + 1] = acc[i][1] + pos[(1 + n) * EMBED + e1 + 1];
        }
        __syncthreads();
    }
}

// ---------------------------------------------------------------------------
// K2: big GEMM  Q[M,512] = Seq[M,512] @ Wq[512,512]^T + bq   (FFMA2 inner)
// tile 128x128, 256 threads, per-thread 8(m, f32x2 pairs) x 8(n, stride 16)
// ---------------------------------------------------------------------------
__global__ __launch_bounds__(256, 2) void qgemm_kernel(
    const float* __restrict__ A, const float* __restrict__ W,
    const float* __restrict__ bias, float* __restrict__ C)
{
    __shared__ float As[16][130];
    __shared__ float Ws[16][130];
    const int t = threadIdx.x;
    const int tm = t >> 4, tn = t & 15;
    const int m0 = blockIdx.y * 128, n0 = blockIdx.x * 128;

    unsigned long long acc[4][8];
    #pragma unroll
    for (int mp = 0; mp < 4; mp++)
        #pragma unroll
        for (int j = 0; j < 8; j++) acc[mp][j] = 0ULL;

    const int row0 = t >> 2, row1 = (t + 256) >> 2;
    const int kq = (t & 3) * 4;

    float4 ra0, ra1, rw0, rw1;
    ra0 = *(const float4*)(A + (size_t)(m0 + row0) * EMBED + kq);
    ra1 = *(const float4*)(A + (size_t)(m0 + row1) * EMBED + kq);
    rw0 = *(const float4*)(W + (size_t)(n0 + row0) * EMBED + kq);
    rw1 = *(const float4*)(W + (size_t)(n0 + row1) * EMBED + kq);

    for (int c = 0; c < 32; c++) {
        As[kq + 0][row0] = ra0.x; As[kq + 1][row0] = ra0.y;
        As[kq + 2][row0] = ra0.z; As[kq + 3][row0] = ra0.w;
        As[kq + 0][row1] = ra1.x; As[kq + 1][row1] = ra1.y;
        As[kq + 2][row1] = ra1.z; As[kq + 3][row1] = ra1.w;
        Ws[kq + 0][row0] = rw0.x; Ws[kq + 1][row0] = rw0.y;
        Ws[kq + 2][row0] = rw0.z; Ws[kq + 3][row0] = rw0.w;
        Ws[kq + 0][row1] = rw1.x; Ws[kq + 1][row1] = rw1.y;
        Ws[kq + 2][row1] = rw1.z; Ws[kq + 3][row1] = rw1.w;
        __syncthreads();
        if (c + 1 < 32) {
            int k0 = (c + 1) * 16;
            ra0 = *(const float4*)(A + (size_t)(m0 + row0) * EMBED + k0 + kq);
            ra1 = *(const float4*)(A + (size_t)(m0 + row1) * EMBED + k0 + kq);
            rw0 = *(const float4*)(W + (size_t)(n0 + row0) * EMBED + k0 + kq);
            rw1 = *(const float4*)(W + (size_t)(n0 + row1) * EMBED + k0 + kq);
        }
        #pragma unroll
        for (int k = 0; k < 16; k++) {
            unsigned long long av[4];
            #pragma unroll
            for (int mp = 0; mp < 4; mp++)
                av[mp] = *(const unsigned long long*)&As[k][tm * 8 + 2 * mp];
            #pragma unroll
            for (int j = 0; j < 8; j++) {
                unsigned long long bd = packdup(Ws[k][tn + 16 * j]);
                #pragma unroll
                for (int mp = 0; mp < 4; mp++) ffma2(acc[mp][j], av[mp], bd);
            }
        }
        __syncthreads();
    }

    #pragma unroll
    for (int j = 0; j < 8; j++) {
        int n = n0 + tn + 16 * j;
        float bb = bias[n];
        #pragma unroll
        for (int mp = 0; mp < 4; mp++) {
            float2 v = unpack2(acc[mp][j]);
            int m = m0 + tm * 8 + 2 * mp;
            C[(size_t)m * EMBED + n]       = v.x + bb;
            C[(size_t)(m + 1) * EMBED + n] = v.y + bb;
        }
    }
}

// ---------------------------------------------------------------------------
// K3: per (b,h): scores = q q^T / 8, column softmax, att row 0 -> ct_pre
// ---------------------------------------------------------------------------
__global__ __launch_bounds__(128) void attn_kernel(
    const float* __restrict__ q, float* __restrict__ ctpre)
{
    __shared__ float qT[HDIM][68];   // [k][s]
    __shared__ float sc[SEQL][68];   // [s][t]
    __shared__ float w0s[SEQL];

    const int b = blockIdx.y, h = blockIdx.x;
    const int t = threadIdx.x, tx = t & 31, ty = t >> 5;
    const float* qb = q + (size_t)b * SEQL * EMBED + h * HDIM;

    for (int idx = t; idx < SEQL * 16; idx += 128) {
        int s = idx >> 4, c4 = (idx & 15) * 4;
        float4 v = *(const float4*)(qb + (size_t)s * EMBED + c4);
        qT[c4 + 0][s] = v.x; qT[c4 + 1][s] = v.y;
        qT[c4 + 2][s] = v.z; qT[c4 + 3][s] = v.w;
    }
    __syncthreads();

    const int c2 = (tx == 0) ? 64 : tx;
    for (int s = ty; s < SEQL; s += 4) {
        float s0 = 0.f, s1 = 0.f, s2 = 0.f;
        #pragma unroll 8
        for (int k = 0; k < HDIM; k++) {
            float qs = qT[k][s];
            s0 += qs * qT[k][tx];
            s1 += qs * qT[k][tx + 32];
            s2 += qs * qT[k][c2];
        }
        sc[s][tx]      = s0 * 0.125f;
        sc[s][tx + 32] = s1 * 0.125f;
        if (tx == 0) sc[s][64] = s2 * 0.125f;
    }
    __syncthreads();

    if (t < SEQL) {
        float m = -1e30f;
        for (int s = 0; s < SEQL; s++) m = fmaxf(m, sc[s][t]);
        float Z = 0.f;
        for (int s = 0; s < SEQL; s++) Z += expf(sc[s][t] - m);
        w0s[t] = expf(sc[0][t] - m) / Z;
    }
    __syncthreads();

    if (t < HDIM) {
        float a = 0.f;
        for (int tt = 0; tt < SEQL; tt++) a += w0s[tt] * qT[t][tt];
        ctpre[(size_t)b * EMBED + h * HDIM + t] = a;
    }
}

// ---------------------------------------------------------------------------
// tail GEMM: C[M,N] = A[M,K] @ W[N,K]^T + bias, optional exact GELU
// ---------------------------------------------------------------------------
__global__ __launch_bounds__(256, 2) void gemm_bias_kernel(
    const float* __restrict__ A, const float* __restrict__ W,
    const float* __restrict__ bias, float* __restrict__ C,
    int M, int N, int K, int act)
{
    __shared__ __align__(16) float As[32][68];
    __shared__ __align__(16) float Ws[32][68];
    const int m0 = blockIdx.y * 64, n0 = blockIdx.x * 64;
    const int t = threadIdx.x;
    const int tn = t & 15, tm = t >> 4;
    float acc[4][4] = {};

    for (int k0 = 0; k0 < K; k0 += 32) {
        #pragma unroll
        for (int l = 0; l < 2; l++) {
            int i = t + l * 256;
            int row = i >> 3;
            int kk = (i & 7) * 4;
            float4 v = *(const float4*)(A + (size_t)(m0 + row) * K + k0 + kk);
            As[kk + 0][row] = v.x; As[kk + 1][row] = v.y;
            As[kk + 2][row] = v.z; As[kk + 3][row] = v.w;
            float4 u = *(const float4*)(W + (size_t)(n0 + row) * K + k0 + kk);
            Ws[kk + 0][row] = u.x; Ws[kk + 1][row] = u.y;
            Ws[kk + 2][row] = u.z; Ws[kk + 3][row] = u.w;
        }
        __syncthreads();
        #pragma unroll
        for (int k = 0; k < 32; k++) {
            float4 av = *(const float4*)&As[k][tm * 4];
            float4 wv = *(const float4*)&Ws[k][tn * 4];
            acc[0][0] += av.x * wv.x; acc[0][1] += av.x * wv.y; acc[0][2] += av.x * wv.z; acc[0][3] += av.x * wv.w;
            acc[1][0] += av.y * wv.x; acc[1][1] += av.y * wv.y; acc[1][2] += av.y * wv.z; acc[1][3] += av.y * wv.w;
            acc[2][0] += av.z * wv.x; acc[2][1] += av.z * wv.y; acc[2][2] += av.z * wv.z; acc[2][3] += av.z * wv.w;
            acc[3][0] += av.w * wv.x; acc[3][1] += av.w * wv.y; acc[3][2] += av.w * wv.z; acc[3][3] += av.w * wv.w;
        }
        __syncthreads();
    }
    #pragma unroll
    for (int i = 0; i < 4; i++) {
        #pragma unroll
        for (int j = 0; j < 4; j++) {
            int m = m0 + tm * 4 + i, n = n0 + tn * 4 + j;
            float v = acc[i][j] + bias[n];
            if (act) v = 0.5f * v * (1.f + erff(v * 0.70710678118654752f));
            C[(size_t)m * N + n] = v;
        }
    }
}

// logits: one CTA per batch row, one warp per class
__global__ __launch_bounds__(320) void logits_kernel(
    const float* __restrict__ h, const float* __restrict__ w2,
    const float* __restrict__ b2, float* __restrict__ out)
{
    int b = blockIdx.x;
    int lane = threadIdx.x & 31, w = threadIdx.x >> 5;
    const float* hb = h + (size_t)b * HID;
    float a = 0.f;
    for (int k = lane; k < HID; k += 32) a += hb[k] * w2[(size_t)w * HID + k];
    #pragma unroll
    for (int o = 16; o > 0; o >>= 1) a += __shfl_xor_sync(0xffffffffu, a, o);
    if (lane == 0) out[(size_t)b * NCLS + w] = a + b2[w];
}

extern "C" void kernel_launch(void* const* d_in, const int* in_sizes, int n_in,
                              void* d_out, int out_size)
{
    const float* x      = (const float*)d_in[0];
    const float* proj_w = (const float*)d_in[1];
    const float* proj_b = (const float*)d_in[2];
    const float* cls    = (const float*)d_in[3];
    const float* pos    = (const float*)d_in[4];
    const float* wq     = (const float*)d_in[5];
    const float* bq     = (const float*)d_in[6];
    const float* wo     = (const float*)d_in[7];
    const float* bo     = (const float*)d_in[8];
    const float* w1     = (const float*)d_in[9];
    const float* b1     = (const float*)d_in[10];
    const float* w2     = (const float*)d_in[11];
    const float* b2     = (const float*)d_in[12];
    float* out = (float*)d_out;

    float *p_seq, *p_q, *p_ctpre, *p_ct, *p_h;
    cudaGetSymbolAddress((void**)&p_seq, g_seq);
    cudaGetSymbolAddress((void**)&p_q, g_q);
    cudaGetSymbolAddress((void**)&p_ctpre, g_ctpre);
    cudaGetSymbolAddress((void**)&p_ct, g_ct);
    cudaGetSymbolAddress((void**)&p_h, g_h);

    seq_kernel<<<BATCH, 256>>>(x, proj_w, proj_b, cls, pos, p_seq);
    qgemm_kernel<<<dim3(EMBED / 128, MTOT / 128), 256>>>(p_seq, wq, bq, p_q);
    attn_kernel<<<dim3(HEADS, BATCH), 128>>>(p_q, p_ctpre);
    gemm_bias_kernel<<<dim3(EMBED / 64, BATCH / 64), 256>>>(
        p_ctpre, wo, bo, p_ct, BATCH, EMBED, EMBED, 0);
    gemm_bias_kernel<<<dim3(HID / 64, BATCH / 64), 256>>>(
        p_ct, w1, b1, p_h, BATCH, HID, EMBED, 1);
    logits_kernel<<<BATCH, 320>>>(p_h, w2, b2, out);
}

// round 4
// speedup vs baseline: 3.9821x; 1.7564x over previous
#include <cuda_runtime.h>
#include <cuda_bf16.h>
#include <math.h>
#include <stdint.h>

#define EMBED 512
#define HEADS 8
#define HDIM 64
#define SEQL 65
#define NPATCH 64
#define PFEAT 48
#define HID 1024
#define NCLS 10
#define BATCH 2048
#define MTOT (BATCH * SEQL)   // 133120

// global scratch (no allocations allowed)
__device__ __align__(16) __nv_bfloat16 g_shi[(size_t)MTOT * EMBED];
__device__ __align__(16) __nv_bfloat16 g_slo[(size_t)MTOT * EMBED];
__device__ __align__(16) __nv_bfloat16 g_whi[EMBED * EMBED];
__device__ __align__(16) __nv_bfloat16 g_wlo[EMBED * EMBED];
__device__ __align__(16) float g_q[(size_t)MTOT * EMBED];
__device__ __align__(16) float g_ctpre[BATCH * EMBED];
__device__ __align__(16) float g_ct[BATCH * EMBED];
__device__ __align__(16) float g_h[BATCH * HID];

// ---------------- helpers ----------------
__device__ __forceinline__ void ffma2(unsigned long long& d,
                                      unsigned long long a,
                                      unsigned long long b) {
    asm("fma.rn.f32x2 %0, %1, %2, %0;" : "+l"(d) : "l"(a), "l"(b));
}
__device__ __forceinline__ unsigned long long packdup(float x) {
    unsigned long long r;
    asm("mov.b64 %0, {%1, %2};" : "=l"(r) : "f"(x), "f"(x));
    return r;
}
__device__ __forceinline__ float2 unpack2(unsigned long long v) {
    float2 r;
    asm("mov.b64 {%0, %1}, %2;" : "=f"(r.x), "=f"(r.y) : "l"(v));
    return r;
}
// fast exp: degree-5 Taylor of 2^f, rel err ~2.4e-6
__device__ __forceinline__ float fexp(float x) {
    x = fmaxf(x, -87.0f);
    float y = x * 1.4426950408889634f;
    int ir = __float2int_rn(y);
    float f = y - (float)ir;
    float p = 1.3333558146428443e-3f;
    p = fmaf(p, f, 9.618129107628477e-3f);
    p = fmaf(p, f, 5.55041086648216e-2f);
    p = fmaf(p, f, 2.402265069591007e-1f);
    p = fmaf(p, f, 6.931471805599453e-1f);
    p = fmaf(p, f, 1.0f);
    return p * __int_as_float((ir + 127) << 23);
}
__device__ __forceinline__ void mma16816(float* c, const uint32_t* a,
                                         const uint32_t* b) {
    asm volatile(
        "mma.sync.aligned.m16n8k16.row.col.f32.bf16.bf16.f32 "
        "{%0,%1,%2,%3}, {%4,%5,%6,%7}, {%8,%9}, {%0,%1,%2,%3};"
        : "+f"(c[0]), "+f"(c[1]), "+f"(c[2]), "+f"(c[3])
        : "r"(a[0]), "r"(a[1]), "r"(a[2]), "r"(a[3]), "r"(b[0]), "r"(b[1]));
}

// ---------------------------------------------------------------------------
// K0: split wq into hi/lo bf16
// ---------------------------------------------------------------------------
__global__ __launch_bounds__(256) void wprep_kernel(
    const float* __restrict__ wq, __nv_bfloat16* __restrict__ whi,
    __nv_bfloat16* __restrict__ wlo)
{
    int i = blockIdx.x * 256 + threadIdx.x;
    float v = wq[i];
    __nv_bfloat16 h = __float2bfloat16(v);
    whi[i] = h;
    wlo[i] = __float2bfloat16(v - __bfloat162float(h));
}

// ---------------------------------------------------------------------------
// K1: one CTA per batch element: patchify -> emb GEMM -> +pos -> hi/lo bf16
// ---------------------------------------------------------------------------
__global__ __launch_bounds__(256) void seq_kernel(
    const float* __restrict__ x, const float* __restrict__ proj_w,
    const float* __restrict__ proj_b, const float* __restrict__ cls,
    const float* __restrict__ pos, __nv_bfloat16* __restrict__ shi_,
    __nv_bfloat16* __restrict__ slo_)
{
    __shared__ float ps[NPATCH * 49];
    __shared__ float wt[PFEAT * 66];

    const int b = blockIdx.x;
    const int t = threadIdx.x;
    const int tx = t & 31, ty = t >> 5;
    __nv_bfloat16* shi = shi_ + (size_t)b * SEQL * EMBED;
    __nv_bfloat16* slo = slo_ + (size_t)b * SEQL * EMBED;

    const float* xb = x + (size_t)b * 3 * 32 * 32;
    for (int idx = t; idx < NPATCH * PFEAT; idx += 256) {
        int n = idx / PFEAT, f = idx % PFEAT;
        int c = f >> 4, r4 = (f >> 2) & 3, c4 = f & 3;
        int py = n >> 3, px = n & 7;
        ps[n * 49 + f] = xb[c * 1024 + (py * 4 + r4) * 32 + (px * 4 + c4)];
    }
    for (int e = t; e < EMBED; e += 256) {
        float v = cls[e] + pos[e];
        __nv_bfloat16 h = __float2bfloat16(v);
        shi[e] = h; slo[e] = __float2bfloat16(v - __bfloat162float(h));
    }
    __syncthreads();

    for (int e0 = 0; e0 < EMBED; e0 += 64) {
        {
            int e = t >> 2, fc = (t & 3) * 12;
            const float4* src = (const float4*)(proj_w + (size_t)(e0 + e) * PFEAT + fc);
            #pragma unroll
            for (int j = 0; j < 3; j++) {
                float4 v = src[j];
                wt[(fc + j * 4 + 0) * 66 + e] = v.x;
                wt[(fc + j * 4 + 1) * 66 + e] = v.y;
                wt[(fc + j * 4 + 2) * 66 + e] = v.z;
                wt[(fc + j * 4 + 3) * 66 + e] = v.w;
            }
        }
        __syncthreads();
        int e1 = e0 + 2 * tx;
        float acc[8][2];
        float pb0 = proj_b[e1], pb1 = proj_b[e1 + 1];
        #pragma unroll
        for (int i = 0; i < 8; i++) { acc[i][0] = pb0; acc[i][1] = pb1; }
        #pragma unroll 4
        for (int f = 0; f < PFEAT; f++) {
            float wv0 = wt[f * 66 + 2 * tx], wv1 = wt[f * 66 + 2 * tx + 1];
            #pragma unroll
            for (int i = 0; i < 8; i++) {
                float pv = ps[(ty + 8 * i) * 49 + f];
                acc[i][0] += pv * wv0; acc[i][1] += pv * wv1;
            }
        }
        #pragma unroll
        for (int i = 0; i < 8; i++) {
            int n = ty + 8 * i;
            #pragma unroll
            for (int u = 0; u < 2; u++) {
                float v = acc[i][u] + pos[(1 + n) * EMBED + e1 + u];
                __nv_bfloat16 h = __float2bfloat16(v);
                shi[(1 + n) * EMBED + e1 + u] = h;
                slo[(1 + n) * EMBED + e1 + u] = __float2bfloat16(v - __bfloat162float(h));
            }
        }
        __syncthreads();
    }
}

// ---------------------------------------------------------------------------
// K2: tensor-core (mma.sync bf16) q GEMM. Q = Seq @ Wq^T + bq, 3-term split.
// CTA tile 128x64, K chunk 32, 8 warps (4m x 2n), warp tile 32x32.
// ---------------------------------------------------------------------------
#define QSTR 40   // smem row stride in bf16 elems (conflict-free: gcd trick)

__global__ __launch_bounds__(256) void qgemm_mma_kernel(
    const __nv_bfloat16* __restrict__ Ahi, const __nv_bfloat16* __restrict__ Alo,
    const __nv_bfloat16* __restrict__ Whi, const __nv_bfloat16* __restrict__ Wlo,
    const float* __restrict__ bias, float* __restrict__ C)
{
    __shared__ __align__(16) __nv_bfloat16 sAh[128 * QSTR];
    __shared__ __align__(16) __nv_bfloat16 sAl[128 * QSTR];
    __shared__ __align__(16) __nv_bfloat16 sWh[64 * QSTR];
    __shared__ __align__(16) __nv_bfloat16 sWl[64 * QSTR];

    const int t = threadIdx.x;
    const int wid = t >> 5, lane = t & 31;
    const int gid = lane >> 2, tig = lane & 3;
    const int wm = wid & 3, wn = wid >> 2;          // 4 x 2 warp grid
    const int m0 = blockIdx.y * 128, n0 = blockIdx.x * 64;

    float acc[2][4][4];
    #pragma unroll
    for (int i = 0; i < 2; i++)
        #pragma unroll
        for (int j = 0; j < 4; j++)
            #pragma unroll
            for (int k = 0; k < 4; k++) acc[i][j][k] = 0.f;

    // prefetch indices: A 512 uint4 per array (2/thread), W 256 (1/thread)
    const int ar0 = t >> 2,        ak0 = (t & 3) * 8;
    const int ar1 = (t + 256) >> 2, ak1 = ak0;
    const int wr  = t >> 2,        wk  = (t & 3) * 8;

    uint4 rah0, rah1, ral0, ral1, rwh, rwl;
    {
        rah0 = *(const uint4*)(Ahi + (size_t)(m0 + ar0) * EMBED + ak0);
        rah1 = *(const uint4*)(Ahi + (size_t)(m0 + ar1) * EMBED + ak1);
        ral0 = *(const uint4*)(Alo + (size_t)(m0 + ar0) * EMBED + ak0);
        ral1 = *(const uint4*)(Alo + (size_t)(m0 + ar1) * EMBED + ak1);
        rwh  = *(const uint4*)(Whi + (size_t)(n0 + wr) * EMBED + wk);
        rwl  = *(const uint4*)(Wlo + (size_t)(n0 + wr) * EMBED + wk);
    }

    for (int c = 0; c < EMBED / 32; c++) {
        *(uint4*)(sAh + ar0 * QSTR + ak0) = rah0;
        *(uint4*)(sAh + ar1 * QSTR + ak1) = rah1;
        *(uint4*)(sAl + ar0 * QSTR + ak0) = ral0;
        *(uint4*)(sAl + ar1 * QSTR + ak1) = ral1;
        *(uint4*)(sWh + wr * QSTR + wk) = rwh;
        *(uint4*)(sWl + wr * QSTR + wk) = rwl;
        __syncthreads();
        if (c + 1 < EMBED / 32) {
            int k0 = (c + 1) * 32;
            rah0 = *(const uint4*)(Ahi + (size_t)(m0 + ar0) * EMBED + k0 + ak0);
            rah1 = *(const uint4*)(Ahi + (size_t)(m0 + ar1) * EMBED + k0 + ak1);
            ral0 = *(const uint4*)(Alo + (size_t)(m0 + ar0) * EMBED + k0 + ak0);
            ral1 = *(const uint4*)(Alo + (size_t)(m0 + ar1) * EMBED + k0 + ak1);
            rwh  = *(const uint4*)(Whi + (size_t)(n0 + wr) * EMBED + k0 + wk);
            rwl  = *(const uint4*)(Wlo + (size_t)(n0 + wr) * EMBED + k0 + wk);
        }
        #pragma unroll
        for (int ks = 0; ks < 2; ks++) {
            const int kb = ks * 16 + tig * 2;
            // A fragments: [mtile][hi/lo][4]
            uint32_t afr[2][2][4];
            #pragma unroll
            for (int mt = 0; mt < 2; mt++) {
                int r = wm * 32 + mt * 16 + gid;
                afr[mt][0][0] = *(const uint32_t*)(sAh + r * QSTR + kb);
                afr[mt][0][1] = *(const uint32_t*)(sAh + (r + 8) * QSTR + kb);
                afr[mt][0][2] = *(const uint32_t*)(sAh + r * QSTR + kb + 8);
                afr[mt][0][3] = *(const uint32_t*)(sAh + (r + 8) * QSTR + kb + 8);
                afr[mt][1][0] = *(const uint32_t*)(sAl + r * QSTR + kb);
                afr[mt][1][1] = *(const uint32_t*)(sAl + (r + 8) * QSTR + kb);
                afr[mt][1][2] = *(const uint32_t*)(sAl + r * QSTR + kb + 8);
                afr[mt][1][3] = *(const uint32_t*)(sAl + (r + 8) * QSTR + kb + 8);
            }
            // B fragments: [ntile][hi/lo][2]
            uint32_t bfr[4][2][2];
            #pragma unroll
            for (int nt = 0; nt < 4; nt++) {
                int nn = wn * 32 + nt * 8 + gid;
                bfr[nt][0][0] = *(const uint32_t*)(sWh + nn * QSTR + kb);
                bfr[nt][0][1] = *(const uint32_t*)(sWh + nn * QSTR + kb + 8);
                bfr[nt][1][0] = *(const uint32_t*)(sWl + nn * QSTR + kb);
                bfr[nt][1][1] = *(const uint32_t*)(sWl + nn * QSTR + kb + 8);
            }
            #pragma unroll
            for (int mt = 0; mt < 2; mt++)
                #pragma unroll
                for (int nt = 0; nt < 4; nt++) {
                    mma16816(acc[mt][nt], afr[mt][0], bfr[nt][0]);  // hi*hi
                    mma16816(acc[mt][nt], afr[mt][0], bfr[nt][1]);  // hi*lo
                    mma16816(acc[mt][nt], afr[mt][1], bfr[nt][0]);  // lo*hi
                }
        }
        __syncthreads();
    }

    #pragma unroll
    for (int mt = 0; mt < 2; mt++) {
        int r = m0 + wm * 32 + mt * 16 + gid;
        #pragma unroll
        for (int nt = 0; nt < 4; nt++) {
            int nn = n0 + wn * 32 + nt * 8 + tig * 2;
            float b0 = bias[nn], b1 = bias[nn + 1];
            C[(size_t)r * EMBED + nn]           = acc[mt][nt][0] + b0;
            C[(size_t)r * EMBED + nn + 1]       = acc[mt][nt][1] + b1;
            C[(size_t)(r + 8) * EMBED + nn]     = acc[mt][nt][2] + b0;
            C[(size_t)(r + 8) * EMBED + nn + 1] = acc[mt][nt][3] + b1;
        }
    }
}

// ---------------------------------------------------------------------------
// K3: per (b,h): scores = q q^T / 8 (f32x2, symmetric), col softmax (poly exp),
// att row 0 -> ct_pre
// ---------------------------------------------------------------------------
__global__ __launch_bounds__(128) void attn_kernel(
    const float* __restrict__ q, float* __restrict__ ctpre)
{
    __shared__ float qT[HDIM][68];   // [k][s]
    __shared__ float sc[SEQL][68];   // [s][t]
    __shared__ float w0s[68];

    const int b = blockIdx.y, h = blockIdx.x;
    const int t = threadIdx.x, lid = t & 31, wid = t >> 5;
    const float* qb = q + (size_t)b * SEQL * EMBED + h * HDIM;

    for (int idx = t; idx < SEQL * 16; idx += 128) {
        int s = idx >> 4, c4 = (idx & 15) * 4;
        float4 v = *(const float4*)(qb + (size_t)s * EMBED + c4);
        qT[c4 + 0][s] = v.x; qT[c4 + 1][s] = v.y;
        qT[c4 + 2][s] = v.z; qT[c4 + 3][s] = v.w;
    }
    __syncthreads();

    const int t2 = 2 * lid;
    unsigned long long sa[17];
    #pragma unroll
    for (int i = 0; i < 17; i++) sa[i] = 0ULL;
    const int r0 = wid * 16;
    #pragma unroll 4
    for (int k = 0; k < HDIM; k++) {
        unsigned long long qt = *(const unsigned long long*)&qT[k][t2];
        #pragma unroll
        for (int i = 0; i < 16; i++) {
            ffma2(sa[i], qt, packdup(qT[k][r0 + i]));
        }
        ffma2(sa[16], qt, packdup(qT[k][64]));
    }
    #pragma unroll
    for (int i = 0; i < 16; i++) {
        float2 v = unpack2(sa[i]);
        sc[r0 + i][t2] = v.x * 0.125f;
        sc[r0 + i][t2 + 1] = v.y * 0.125f;
    }
    if (wid == 0) {
        float2 v = unpack2(sa[16]);
        sc[64][t2] = v.x * 0.125f;
        sc[64][t2 + 1] = v.y * 0.125f;
    }
    __syncthreads();
    if (t < 64) sc[t][64] = sc[64][t];
    if (t == 64) {
        float a = 0.f;
        for (int k = 0; k < HDIM; k++) a += qT[k][64] * qT[k][64];
        sc[64][64] = a * 0.125f;
    }
    __syncthreads();

    if (t < SEQL) {
        float m = -1e30f;
        for (int s = 0; s < SEQL; s++) m = fmaxf(m, sc[s][t]);
        float Z = 0.f;
        for (int s = 0; s < SEQL; s++) Z += fexp(sc[s][t] - m);
        w0s[t] = fexp(sc[0][t] - m) / Z;
    }
    __syncthreads();

    if (t < HDIM) {
        float a = 0.f;
        for (int tt = 0; tt < SEQL; tt++) a += w0s[tt] * qT[t][tt];
        ctpre[(size_t)b * EMBED + h * HDIM + t] = a;
    }
}

// ---------------------------------------------------------------------------
// tail GEMM: C[M,N] = A[M,K] @ W[N,K]^T + bias, optional exact GELU
// ---------------------------------------------------------------------------
__global__ __launch_bounds__(256, 2) void gemm_bias_kernel(
    const float* __restrict__ A, const float* __restrict__ W,
    const float* __restrict__ bias, float* __restrict__ C,
    int M, int N, int K, int act)
{
    __shared__ __align__(16) float As[32][68];
    __shared__ __align__(16) float Ws[32][68];
    const int m0 = blockIdx.y * 64, n0 = blockIdx.x * 64;
    const int t = threadIdx.x;
    const int tn = t & 15, tm = t >> 4;
    float acc[4][4] = {};

    for (int k0 = 0; k0 < K; k0 += 32) {
        #pragma unroll
        for (int l = 0; l < 2; l++) {
            int i = t + l * 256;
            int row = i >> 3;
            int kk = (i & 7) * 4;
            float4 v = *(const float4*)(A + (size_t)(m0 + row) * K + k0 + kk);
            As[kk + 0][row] = v.x; As[kk + 1][row] = v.y;
            As[kk + 2][row] = v.z; As[kk + 3][row] = v.w;
            float4 u = *(const float4*)(W + (size_t)(n0 + row) * K + k0 + kk);
            Ws[kk + 0][row] = u.x; Ws[kk + 1][row] = u.y;
            Ws[kk + 2][row] = u.z; Ws[kk + 3][row] = u.w;
        }
        __syncthreads();
        #pragma unroll
        for (int k = 0; k < 32; k++) {
            float4 av = *(const float4*)&As[k][tm * 4];
            float4 wv = *(const float4*)&Ws[k][tn * 4];
            acc[0][0] += av.x * wv.x; acc[0][1] += av.x * wv.y; acc[0][2] += av.x * wv.z; acc[0][3] += av.x * wv.w;
            acc[1][0] += av.y * wv.x; acc[1][1] += av.y * wv.y; acc[1][2] += av.y * wv.z; acc[1][3] += av.y * wv.w;
            acc[2][0] += av.z * wv.x; acc[2][1] += av.z * wv.y; acc[2][2] += av.z * wv.z; acc[2][3] += av.z * wv.w;
            acc[3][0] += av.w * wv.x; acc[3][1] += av.w * wv.y; acc[3][2] += av.w * wv.z; acc[3][3] += av.w * wv.w;
        }
        __syncthreads();
    }
    #pragma unroll
    for (int i = 0; i < 4; i++) {
        #pragma unroll
        for (int j = 0; j < 4; j++) {
            int m = m0 + tm * 4 + i, n = n0 + tn * 4 + j;
            float v = acc[i][j] + bias[n];
            if (act) v = 0.5f * v * (1.f + erff(v * 0.70710678118654752f));
            C[(size_t)m * N + n] = v;
        }
    }
}

// logits: one CTA per batch row, one warp per class
__global__ __launch_bounds__(320) void logits_kernel(
    const float* __restrict__ h, const float* __restrict__ w2,
    const float* __restrict__ b2, float* __restrict__ out)
{
    int b = blockIdx.x;
    int lane = threadIdx.x & 31, w = threadIdx.x >> 5;
    const float* hb = h + (size_t)b * HID;
    float a = 0.f;
    for (int k = lane; k < HID; k += 32) a += hb[k] * w2[(size_t)w * HID + k];
    #pragma unroll
    for (int o = 16; o > 0; o >>= 1) a += __shfl_xor_sync(0xffffffffu, a, o);
    if (lane == 0) out[(size_t)b * NCLS + w] = a + b2[w];
}

extern "C" void kernel_launch(void* const* d_in, const int* in_sizes, int n_in,
                              void* d_out, int out_size)
{
    const float* x      = (const float*)d_in[0];
    const float* proj_w = (const float*)d_in[1];
    const float* proj_b = (const float*)d_in[2];
    const float* cls    = (const float*)d_in[3];
    const float* pos    = (const float*)d_in[4];
    const float* wq     = (const float*)d_in[5];
    const float* bq     = (const float*)d_in[6];
    const float* wo     = (const float*)d_in[7];
    const float* bo     = (const float*)d_in[8];
    const float* w1     = (const float*)d_in[9];
    const float* b1     = (const float*)d_in[10];
    const float* w2     = (const float*)d_in[11];
    const float* b2     = (const float*)d_in[12];
    float* out = (float*)d_out;

    __nv_bfloat16 *p_shi, *p_slo, *p_whi, *p_wlo;
    float *p_q, *p_ctpre, *p_ct, *p_h;
    cudaGetSymbolAddress((void**)&p_shi, g_shi);
    cudaGetSymbolAddress((void**)&p_slo, g_slo);
    cudaGetSymbolAddress((void**)&p_whi, g_whi);
    cudaGetSymbolAddress((void**)&p_wlo, g_wlo);
    cudaGetSymbolAddress((void**)&p_q, g_q);
    cudaGetSymbolAddress((void**)&p_ctpre, g_ctpre);
    cudaGetSymbolAddress((void**)&p_ct, g_ct);
    cudaGetSymbolAddress((void**)&p_h, g_h);

    wprep_kernel<<<EMBED * EMBED / 256, 256>>>(wq, p_whi, p_wlo);
    seq_kernel<<<BATCH, 256>>>(x, proj_w, proj_b, cls, pos, p_shi, p_slo);
    qgemm_mma_kernel<<<dim3(EMBED / 64, MTOT / 128), 256>>>(
        p_shi, p_slo, p_whi, p_wlo, bq, p_q);
    attn_kernel<<<dim3(HEADS, BATCH), 128>>>(p_q, p_ctpre);
    gemm_bias_kernel<<<dim3(EMBED / 64, BATCH / 64), 256>>>(
        p_ctpre, wo, bo, p_ct, BATCH, EMBED, EMBED, 0);
    gemm_bias_kernel<<<dim3(HID / 64, BATCH / 64), 256>>>(
        p_ct, w1, b1, p_h, BATCH, HID, EMBED, 1);
    logits_kernel<<<BATCH, 320>>>(p_h, w2, b2, out);
}

// round 5
// speedup vs baseline: 4.1800x; 1.0497x over previous
#include <cuda_runtime.h>
#include <cuda_bf16.h>
#include <math.h>
#include <stdint.h>

#define EMBED 512
#define HEADS 8
#define HDIM 64
#define SEQL 65
#define NPATCH 64
#define PFEAT 48
#define HID 1024
#define NCLS 10
#define BATCH 2048
#define MTOT (BATCH * SEQL)   // 133120

// global scratch (no allocations allowed)
__device__ __align__(16) __nv_bfloat16 g_shi[(size_t)MTOT * EMBED];
__device__ __align__(16) __nv_bfloat16 g_slo[(size_t)MTOT * EMBED];
__device__ __align__(16) __nv_bfloat16 g_whi[EMBED * EMBED];
__device__ __align__(16) __nv_bfloat16 g_wlo[EMBED * EMBED];
__device__ __align__(16) float g_q[(size_t)MTOT * EMBED];
__device__ __align__(16) float g_ctpre[BATCH * EMBED];
__device__ __align__(16) float g_ct[BATCH * EMBED];
__device__ __align__(16) float g_h[BATCH * HID];

// ---------------- helpers ----------------
__device__ __forceinline__ void ffma2(unsigned long long& d,
                                      unsigned long long a,
                                      unsigned long long b) {
    asm("fma.rn.f32x2 %0, %1, %2, %0;" : "+l"(d) : "l"(a), "l"(b));
}
__device__ __forceinline__ unsigned long long packdup(float x) {
    unsigned long long r;
    asm("mov.b64 %0, {%1, %2};" : "=l"(r) : "f"(x), "f"(x));
    return r;
}
__device__ __forceinline__ float2 unpack2(unsigned long long v) {
    float2 r;
    asm("mov.b64 {%0, %1}, %2;" : "=f"(r.x), "=f"(r.y) : "l"(v));
    return r;
}
// fast exp: degree-5 Taylor of 2^f, rel err ~2.4e-6
__device__ __forceinline__ float fexp(float x) {
    x = fmaxf(x, -87.0f);
    float y = x * 1.4426950408889634f;
    int ir = __float2int_rn(y);
    float f = y - (float)ir;
    float p = 1.3333558146428443e-3f;
    p = fmaf(p, f, 9.618129107628477e-3f);
    p = fmaf(p, f, 5.55041086648216e-2f);
    p = fmaf(p, f, 2.402265069591007e-1f);
    p = fmaf(p, f, 6.931471805599453e-1f);
    p = fmaf(p, f, 1.0f);
    return p * __int_as_float((ir + 127) << 23);
}
__device__ __forceinline__ void mma16816(float* c, const uint32_t* a,
                                         const uint32_t* b) {
    asm volatile(
        "mma.sync.aligned.m16n8k16.row.col.f32.bf16.bf16.f32 "
        "{%0,%1,%2,%3}, {%4,%5,%6,%7}, {%8,%9}, {%0,%1,%2,%3};"
        : "+f"(c[0]), "+f"(c[1]), "+f"(c[2]), "+f"(c[3])
        : "r"(a[0]), "r"(a[1]), "r"(a[2]), "r"(a[3]), "r"(b[0]), "r"(b[1]));
}
// cp.async helpers (sm_80+, valid on base sm_103 target)
__device__ __forceinline__ void cp16(uint32_t dst_smem, const void* src) {
    asm volatile("cp.async.ca.shared.global [%0], [%1], 16;"
                 :: "r"(dst_smem), "l"(src));
}
__device__ __forceinline__ void cpcommit() {
    asm volatile("cp.async.commit_group;");
}
__device__ __forceinline__ void cpwait1() {
    asm volatile("cp.async.wait_group 1;");
}
__device__ __forceinline__ void cpwait0() {
    asm volatile("cp.async.wait_group 0;");
}

// ---------------------------------------------------------------------------
// K0: split wq into hi/lo bf16
// ---------------------------------------------------------------------------
__global__ __launch_bounds__(256) void wprep_kernel(
    const float* __restrict__ wq, __nv_bfloat16* __restrict__ whi,
    __nv_bfloat16* __restrict__ wlo)
{
    int i = blockIdx.x * 256 + threadIdx.x;
    float v = wq[i];
    __nv_bfloat16 h = __float2bfloat16(v);
    whi[i] = h;
    wlo[i] = __float2bfloat16(v - __bfloat162float(h));
}

// ---------------------------------------------------------------------------
// K1: one CTA per batch element: patchify -> emb GEMM -> +pos -> hi/lo bf16
// ---------------------------------------------------------------------------
__global__ __launch_bounds__(256) void seq_kernel(
    const float* __restrict__ x, const float* __restrict__ proj_w,
    const float* __restrict__ proj_b, const float* __restrict__ cls,
    const float* __restrict__ pos, __nv_bfloat16* __restrict__ shi_,
    __nv_bfloat16* __restrict__ slo_)
{
    __shared__ float ps[NPATCH * 49];
    __shared__ float wt[PFEAT * 66];

    const int b = blockIdx.x;
    const int t = threadIdx.x;
    const int tx = t & 31, ty = t >> 5;
    __nv_bfloat16* shi = shi_ + (size_t)b * SEQL * EMBED;
    __nv_bfloat16* slo = slo_ + (size_t)b * SEQL * EMBED;

    const float* xb = x + (size_t)b * 3 * 32 * 32;
    for (int idx = t; idx < NPATCH * PFEAT; idx += 256) {
        int n = idx / PFEAT, f = idx % PFEAT;
        int c = f >> 4, r4 = (f >> 2) & 3, c4 = f & 3;
        int py = n >> 3, px = n & 7;
        ps[n * 49 + f] = xb[c * 1024 + (py * 4 + r4) * 32 + (px * 4 + c4)];
    }
    for (int e = t; e < EMBED; e += 256) {
        float v = cls[e] + pos[e];
        __nv_bfloat16 h = __float2bfloat16(v);
        shi[e] = h; slo[e] = __float2bfloat16(v - __bfloat162float(h));
    }
    __syncthreads();

    for (int e0 = 0; e0 < EMBED; e0 += 64) {
        {
            int e = t >> 2, fc = (t & 3) * 12;
            const float4* src = (const float4*)(proj_w + (size_t)(e0 + e) * PFEAT + fc);
            #pragma unroll
            for (int j = 0; j < 3; j++) {
                float4 v = src[j];
                wt[(fc + j * 4 + 0) * 66 + e] = v.x;
                wt[(fc + j * 4 + 1) * 66 + e] = v.y;
                wt[(fc + j * 4 + 2) * 66 + e] = v.z;
                wt[(fc + j * 4 + 3) * 66 + e] = v.w;
            }
        }
        __syncthreads();
        int e1 = e0 + 2 * tx;
        float acc[8][2];
        float pb0 = proj_b[e1], pb1 = proj_b[e1 + 1];
        #pragma unroll
        for (int i = 0; i < 8; i++) { acc[i][0] = pb0; acc[i][1] = pb1; }
        #pragma unroll 4
        for (int f = 0; f < PFEAT; f++) {
            float wv0 = wt[f * 66 + 2 * tx], wv1 = wt[f * 66 + 2 * tx + 1];
            #pragma unroll
            for (int i = 0; i < 8; i++) {
                float pv = ps[(ty + 8 * i) * 49 + f];
                acc[i][0] += pv * wv0; acc[i][1] += pv * wv1;
            }
        }
        #pragma unroll
        for (int i = 0; i < 8; i++) {
            int n = ty + 8 * i;
            #pragma unroll
            for (int u = 0; u < 2; u++) {
                float v = acc[i][u] + pos[(1 + n) * EMBED + e1 + u];
                __nv_bfloat16 h = __float2bfloat16(v);
                shi[(1 + n) * EMBED + e1 + u] = h;
                slo[(1 + n) * EMBED + e1 + u] = __float2bfloat16(v - __bfloat162float(h));
            }
        }
        __syncthreads();
    }
}

// ---------------------------------------------------------------------------
// K2: tensor-core (mma.sync bf16) q GEMM, cp.async double-buffered.
// CTA tile 128x64, K chunk 32, 8 warps (4m x 2n), warp tile 32x32.
// ---------------------------------------------------------------------------
#define QSTR 40   // smem row stride in bf16 elems
#define NCH 16    // 512/32 K-chunks

__global__ __launch_bounds__(256, 2) void qgemm_mma_kernel(
    const __nv_bfloat16* __restrict__ Ahi, const __nv_bfloat16* __restrict__ Alo,
    const __nv_bfloat16* __restrict__ Whi, const __nv_bfloat16* __restrict__ Wlo,
    const float* __restrict__ bias, float* __restrict__ C)
{
    __shared__ __align__(16) __nv_bfloat16 sAh[2][128 * QSTR];
    __shared__ __align__(16) __nv_bfloat16 sAl[2][128 * QSTR];
    __shared__ __align__(16) __nv_bfloat16 sWh[2][64 * QSTR];
    __shared__ __align__(16) __nv_bfloat16 sWl[2][64 * QSTR];

    const int t = threadIdx.x;
    const int wid = t >> 5, lane = t & 31;
    const int gid = lane >> 2, tig = lane & 3;
    const int wm = wid & 3, wn = wid >> 2;          // 4 x 2 warp grid
    const int m0 = blockIdx.y * 128, n0 = blockIdx.x * 64;

    float acc[2][4][4];
    #pragma unroll
    for (int i = 0; i < 2; i++)
        #pragma unroll
        for (int j = 0; j < 4; j++)
            #pragma unroll
            for (int k = 0; k < 4; k++) acc[i][j][k] = 0.f;

    const int ar0 = t >> 2,         ak = (t & 3) * 8;
    const int ar1 = (t + 256) >> 2;
    const int wr  = t >> 2;

    const uint32_t dAh0 = (uint32_t)__cvta_generic_to_shared(&sAh[0][ar0 * QSTR + ak]);
    const uint32_t dAh1 = (uint32_t)__cvta_generic_to_shared(&sAh[0][ar1 * QSTR + ak]);
    const uint32_t dAl0 = (uint32_t)__cvta_generic_to_shared(&sAl[0][ar0 * QSTR + ak]);
    const uint32_t dAl1 = (uint32_t)__cvta_generic_to_shared(&sAl[0][ar1 * QSTR + ak]);
    const uint32_t dWh  = (uint32_t)__cvta_generic_to_shared(&sWh[0][wr * QSTR + ak]);
    const uint32_t dWl  = (uint32_t)__cvta_generic_to_shared(&sWl[0][wr * QSTR + ak]);
    const uint32_t stA = 128 * QSTR * 2;   // bytes per A stage
    const uint32_t stW = 64 * QSTR * 2;    // bytes per W stage

    // issue chunk c into stage s
    auto issue = [&](int c, int s) {
        size_t ko = (size_t)c * 32 + ak;
        cp16(dAh0 + s * stA, Ahi + (size_t)(m0 + ar0) * EMBED + ko);
        cp16(dAh1 + s * stA, Ahi + (size_t)(m0 + ar1) * EMBED + ko);
        cp16(dAl0 + s * stA, Alo + (size_t)(m0 + ar0) * EMBED + ko);
        cp16(dAl1 + s * stA, Alo + (size_t)(m0 + ar1) * EMBED + ko);
        cp16(dWh + s * stW, Whi + (size_t)(n0 + wr) * EMBED + ko);
        cp16(dWl + s * stW, Wlo + (size_t)(n0 + wr) * EMBED + ko);
        cpcommit();
    };

    issue(0, 0);
    for (int c = 0; c < NCH; c++) {
        const int s = c & 1;
        if (c + 1 < NCH) { issue(c + 1, (c + 1) & 1); cpwait1(); }
        else             { cpwait0(); }
        __syncthreads();
        const __nv_bfloat16* pAh = sAh[s];
        const __nv_bfloat16* pAl = sAl[s];
        const __nv_bfloat16* pWh = sWh[s];
        const __nv_bfloat16* pWl = sWl[s];
        #pragma unroll
        for (int ks = 0; ks < 2; ks++) {
            const int kb = ks * 16 + tig * 2;
            uint32_t afr[2][2][4];
            #pragma unroll
            for (int mt = 0; mt < 2; mt++) {
                int r = wm * 32 + mt * 16 + gid;
                afr[mt][0][0] = *(const uint32_t*)(pAh + r * QSTR + kb);
                afr[mt][0][1] = *(const uint32_t*)(pAh + (r + 8) * QSTR + kb);
                afr[mt][0][2] = *(const uint32_t*)(pAh + r * QSTR + kb + 8);
                afr[mt][0][3] = *(const uint32_t*)(pAh + (r + 8) * QSTR + kb + 8);
                afr[mt][1][0] = *(const uint32_t*)(pAl + r * QSTR + kb);
                afr[mt][1][1] = *(const uint32_t*)(pAl + (r + 8) * QSTR + kb);
                afr[mt][1][2] = *(const uint32_t*)(pAl + r * QSTR + kb + 8);
                afr[mt][1][3] = *(const uint32_t*)(pAl + (r + 8) * QSTR + kb + 8);
            }
            uint32_t bfr[4][2][2];
            #pragma unroll
            for (int nt = 0; nt < 4; nt++) {
                int nn = wn * 32 + nt * 8 + gid;
                bfr[nt][0][0] = *(const uint32_t*)(pWh + nn * QSTR + kb);
                bfr[nt][0][1] = *(const uint32_t*)(pWh + nn * QSTR + kb + 8);
                bfr[nt][1][0] = *(const uint32_t*)(pWl + nn * QSTR + kb);
                bfr[nt][1][1] = *(const uint32_t*)(pWl + nn * QSTR + kb + 8);
            }
            #pragma unroll
            for (int mt = 0; mt < 2; mt++)
                #pragma unroll
                for (int nt = 0; nt < 4; nt++) {
                    mma16816(acc[mt][nt], afr[mt][0], bfr[nt][0]);  // hi*hi
                    mma16816(acc[mt][nt], afr[mt][0], bfr[nt][1]);  // hi*lo
                    mma16816(acc[mt][nt], afr[mt][1], bfr[nt][0]);  // lo*hi
                }
        }
        __syncthreads();
    }

    #pragma unroll
    for (int mt = 0; mt < 2; mt++) {
        int r = m0 + wm * 32 + mt * 16 + gid;
        #pragma unroll
        for (int nt = 0; nt < 4; nt++) {
            int nn = n0 + wn * 32 + nt * 8 + tig * 2;
            float b0 = bias[nn], b1 = bias[nn + 1];
            C[(size_t)r * EMBED + nn]           = acc[mt][nt][0] + b0;
            C[(size_t)r * EMBED + nn + 1]       = acc[mt][nt][1] + b1;
            C[(size_t)(r + 8) * EMBED + nn]     = acc[mt][nt][2] + b0;
            C[(size_t)(r + 8) * EMBED + nn + 1] = acc[mt][nt][3] + b1;
        }
    }
}

// ---------------------------------------------------------------------------
// K3: per (b,h): scores = q q^T / 8 (f32x2 + float4 row broadcasts),
// col softmax (poly exp), att row 0 -> ct_pre
// ---------------------------------------------------------------------------
__global__ __launch_bounds__(128) void attn_kernel(
    const float* __restrict__ q, float* __restrict__ ctpre)
{
    __shared__ __align__(16) float qT[HDIM][68];   // [k][s]
    __shared__ float sc[SEQL][68];                 // [s][t]
    __shared__ float w0s[68];

    const int b = blockIdx.y, h = blockIdx.x;
    const int t = threadIdx.x, lid = t & 31, wid = t >> 5;
    const float* qb = q + (size_t)b * SEQL * EMBED + h * HDIM;

    for (int idx = t; idx < SEQL * 16; idx += 128) {
        int s = idx >> 4, c4 = (idx & 15) * 4;
        float4 v = *(const float4*)(qb + (size_t)s * EMBED + c4);
        qT[c4 + 0][s] = v.x; qT[c4 + 1][s] = v.y;
        qT[c4 + 2][s] = v.z; qT[c4 + 3][s] = v.w;
    }
    __syncthreads();

    // warp w -> rows w*16..+15 (+row 64 on warp 0's slot 16), cols (2*lid, 2*lid+1)
    const int t2 = 2 * lid;
    unsigned long long sa[17];
    #pragma unroll
    for (int i = 0; i < 17; i++) sa[i] = 0ULL;
    const int r0 = wid * 16;
    #pragma unroll 2
    for (int k = 0; k < HDIM; k++) {
        unsigned long long qt = *(const unsigned long long*)&qT[k][t2];
        float4 ra = *(const float4*)&qT[k][r0];
        float4 rb = *(const float4*)&qT[k][r0 + 4];
        float4 rc = *(const float4*)&qT[k][r0 + 8];
        float4 rd = *(const float4*)&qT[k][r0 + 12];
        float r64 = qT[k][64];
        ffma2(sa[0],  qt, packdup(ra.x)); ffma2(sa[1],  qt, packdup(ra.y));
        ffma2(sa[2],  qt, packdup(ra.z)); ffma2(sa[3],  qt, packdup(ra.w));
        ffma2(sa[4],  qt, packdup(rb.x)); ffma2(sa[5],  qt, packdup(rb.y));
        ffma2(sa[6],  qt, packdup(rb.z)); ffma2(sa[7],  qt, packdup(rb.w));
        ffma2(sa[8],  qt, packdup(rc.x)); ffma2(sa[9],  qt, packdup(rc.y));
        ffma2(sa[10], qt, packdup(rc.z)); ffma2(sa[11], qt, packdup(rc.w));
        ffma2(sa[12], qt, packdup(rd.x)); ffma2(sa[13], qt, packdup(rd.y));
        ffma2(sa[14], qt, packdup(rd.z)); ffma2(sa[15], qt, packdup(rd.w));
        ffma2(sa[16], qt, packdup(r64));
    }
    #pragma unroll
    for (int i = 0; i < 16; i++) {
        float2 v = unpack2(sa[i]);
        sc[r0 + i][t2] = v.x * 0.125f;
        sc[r0 + i][t2 + 1] = v.y * 0.125f;
    }
    if (wid == 0) {
        float2 v = unpack2(sa[16]);
        sc[64][t2] = v.x * 0.125f;
        sc[64][t2 + 1] = v.y * 0.125f;
    }
    __syncthreads();
    if (t < 64) sc[t][64] = sc[64][t];
    if (t == 64) {
        float a = 0.f;
        for (int k = 0; k < HDIM; k++) a += qT[k][64] * qT[k][64];
        sc[64][64] = a * 0.125f;
    }
    __syncthreads();

    if (t < SEQL) {
        float m = -1e30f;
        for (int s = 0; s < SEQL; s++) m = fmaxf(m, sc[s][t]);
        float Z = 0.f;
        for (int s = 0; s < SEQL; s++) Z += fexp(sc[s][t] - m);
        w0s[t] = fexp(sc[0][t] - m) / Z;
    }
    __syncthreads();

    if (t < HDIM) {
        float a = 0.f;
        for (int tt = 0; tt < SEQL; tt++) a += w0s[tt] * qT[t][tt];
        ctpre[(size_t)b * EMBED + h * HDIM + t] = a;
    }
}

// ---------------------------------------------------------------------------
// tail GEMM: C[M,N] = A[M,K] @ W[N,K]^T + bias, optional exact GELU
// ---------------------------------------------------------------------------
__global__ __launch_bounds__(256, 2) void gemm_bias_kernel(
    const float* __restrict__ A, const float* __restrict__ W,
    const float* __restrict__ bias, float* __restrict__ C,
    int M, int N, int K, int act)
{
    __shared__ __align__(16) float As[32][68];
    __shared__ __align__(16) float Ws[32][68];
    const int m0 = blockIdx.y * 64, n0 = blockIdx.x * 64;
    const int t = threadIdx.x;
    const int tn = t & 15, tm = t >> 4;
    float acc[4][4] = {};

    for (int k0 = 0; k0 < K; k0 += 32) {
        #pragma unroll
        for (int l = 0; l < 2; l++) {
            int i = t + l * 256;
            int row = i >> 3;
            int kk = (i & 7) * 4;
            float4 v = *(const float4*)(A + (size_t)(m0 + row) * K + k0 + kk);
            As[kk + 0][row] = v.x; As[kk + 1][row] = v.y;
            As[kk + 2][row] = v.z; As[kk + 3][row] = v.w;
            float4 u = *(const float4*)(W + (size_t)(n0 + row) * K + k0 + kk);
            Ws[kk + 0][row] = u.x; Ws[kk + 1][row] = u.y;
            Ws[kk + 2][row] = u.z; Ws[kk + 3][row] = u.w;
        }
        __syncthreads();
        #pragma unroll
        for (int k = 0; k < 32; k++) {
            float4 av = *(const float4*)&As[k][tm * 4];
            float4 wv = *(const float4*)&Ws[k][tn * 4];
            acc[0][0] += av.x * wv.x; acc[0][1] += av.x * wv.y; acc[0][2] += av.x * wv.z; acc[0][3] += av.x * wv.w;
            acc[1][0] += av.y * wv.x; acc[1][1] += av.y * wv.y; acc[1][2] += av.y * wv.z; acc[1][3] += av.y * wv.w;
            acc[2][0] += av.z * wv.x; acc[2][1] += av.z * wv.y; acc[2][2] += av.z * wv.z; acc[2][3] += av.z * wv.w;
            acc[3][0] += av.w * wv.x; acc[3][1] += av.w * wv.y; acc[3][2] += av.w * wv.z; acc[3][3] += av.w * wv.w;
        }
        __syncthreads();
    }
    #pragma unroll
    for (int i = 0; i < 4; i++) {
        #pragma unroll
        for (int j = 0; j < 4; j++) {
            int m = m0 + tm * 4 + i, n = n0 + tn * 4 + j;
            float v = acc[i][j] + bias[n];
            if (act) v = 0.5f * v * (1.f + erff(v * 0.70710678118654752f));
            C[(size_t)m * N + n] = v;
        }
    }
}

// logits: one CTA per batch row, one warp per class
__global__ __launch_bounds__(320) void logits_kernel(
    const float* __restrict__ h, const float* __restrict__ w2,
    const float* __restrict__ b2, float* __restrict__ out)
{
    int b = blockIdx.x;
    int lane = threadIdx.x & 31, w = threadIdx.x >> 5;
    const float* hb = h + (size_t)b * HID;
    float a = 0.f;
    for (int k = lane; k < HID; k += 32) a += hb[k] * w2[(size_t)w * HID + k];
    #pragma unroll
    for (int o = 16; o > 0; o >>= 1) a += __shfl_xor_sync(0xffffffffu, a, o);
    if (lane == 0) out[(size_t)b * NCLS + w] = a + b2[w];
}

extern "C" void kernel_launch(void* const* d_in, const int* in_sizes, int n_in,
                              void* d_out, int out_size)
{
    const float* x      = (const float*)d_in[0];
    const float* proj_w = (const float*)d_in[1];
    const float* proj_b = (const float*)d_in[2];
    const float* cls    = (const float*)d_in[3];
    const float* pos    = (const float*)d_in[4];
    const float* wq     = (const float*)d_in[5];
    const float* bq     = (const float*)d_in[6];
    const float* wo     = (const float*)d_in[7];
    const float* bo     = (const float*)d_in[8];
    const float* w1     = (const float*)d_in[9];
    const float* b1     = (const float*)d_in[10];
    const float* w2     = (const float*)d_in[11];
    const float* b2     = (const float*)d_in[12];
    float* out = (float*)d_out;

    __nv_bfloat16 *p_shi, *p_slo, *p_whi, *p_wlo;
    float *p_q, *p_ctpre, *p_ct, *p_h;
    cudaGetSymbolAddress((void**)&p_shi, g_shi);
    cudaGetSymbolAddress((void**)&p_slo, g_slo);
    cudaGetSymbolAddress((void**)&p_whi, g_whi);
    cudaGetSymbolAddress((void**)&p_wlo, g_wlo);
    cudaGetSymbolAddress((void**)&p_q, g_q);
    cudaGetSymbolAddress((void**)&p_ctpre, g_ctpre);
    cudaGetSymbolAddress((void**)&p_ct, g_ct);
    cudaGetSymbolAddress((void**)&p_h, g_h);

    wprep_kernel<<<EMBED * EMBED / 256, 256>>>(wq, p_whi, p_wlo);
    seq_kernel<<<BATCH, 256>>>(x, proj_w, proj_b, cls, pos, p_shi, p_slo);
    qgemm_mma_kernel<<<dim3(EMBED / 64, MTOT / 128), 256>>>(
        p_shi, p_slo, p_whi, p_wlo, bq, p_q);
    attn_kernel<<<dim3(HEADS, BATCH), 128>>>(p_q, p_ctpre);
    gemm_bias_kernel<<<dim3(EMBED / 64, BATCH / 64), 256>>>(
        p_ctpre, wo, bo, p_ct, BATCH, EMBED, EMBED, 0);
    gemm_bias_kernel<<<dim3(HID / 64, BATCH / 64), 256>>>(
        p_ct, w1, b1, p_h, BATCH, HID, EMBED, 1);
    logits_kernel<<<BATCH, 320>>>(p_h, w2, b2, out);
}

// round 6
// speedup vs baseline: 5.0287x; 1.2030x over previous
#include <cuda_runtime.h>
#include <cuda_bf16.h>
#include <math.h>
#include <stdint.h>

#define EMBED 512
#define HEADS 8
#define HDIM 64
#define SEQL 65
#define NPATCH 64
#define PFEAT 48
#define HID 1024
#define NCLS 10
#define BATCH 2048
#define MTOT (BATCH * SEQL)   // 133120

// global scratch (no allocations allowed)
__device__ __align__(16) __nv_bfloat16 g_shi[(size_t)MTOT * EMBED];
__device__ __align__(16) __nv_bfloat16 g_slo[(size_t)MTOT * EMBED];
__device__ __align__(16) __nv_bfloat16 g_whi[EMBED * EMBED];
__device__ __align__(16) __nv_bfloat16 g_wlo[EMBED * EMBED];
__device__ __align__(16) __nv_bfloat16 g_qhi[(size_t)MTOT * EMBED];
__device__ __align__(16) __nv_bfloat16 g_qlo[(size_t)MTOT * EMBED];
__device__ __align__(16) float g_ctpre[BATCH * EMBED];
__device__ __align__(16) float g_ct[BATCH * EMBED];
__device__ __align__(16) float g_h[BATCH * HID];

// ---------------- helpers ----------------
// fast exp: degree-5 Taylor of 2^f, rel err ~2.4e-6
__device__ __forceinline__ float fexp(float x) {
    x = fmaxf(x, -87.0f);
    float y = x * 1.4426950408889634f;
    int ir = __float2int_rn(y);
    float f = y - (float)ir;
    float p = 1.3333558146428443e-3f;
    p = fmaf(p, f, 9.618129107628477e-3f);
    p = fmaf(p, f, 5.55041086648216e-2f);
    p = fmaf(p, f, 2.402265069591007e-1f);
    p = fmaf(p, f, 6.931471805599453e-1f);
    p = fmaf(p, f, 1.0f);
    return p * __int_as_float((ir + 127) << 23);
}
__device__ __forceinline__ void mma16816(float* c, const uint32_t* a,
                                         const uint32_t* b) {
    asm volatile(
        "mma.sync.aligned.m16n8k16.row.col.f32.bf16.bf16.f32 "
        "{%0,%1,%2,%3}, {%4,%5,%6,%7}, {%8,%9}, {%0,%1,%2,%3};"
        : "+f"(c[0]), "+f"(c[1]), "+f"(c[2]), "+f"(c[3])
        : "r"(a[0]), "r"(a[1]), "r"(a[2]), "r"(a[3]), "r"(b[0]), "r"(b[1]));
}
__device__ __forceinline__ void ldsm4(uint32_t* r, uint32_t addr) {
    asm volatile("ldmatrix.sync.aligned.m8n8.x4.shared.b16 {%0,%1,%2,%3}, [%4];"
                 : "=r"(r[0]), "=r"(r[1]), "=r"(r[2]), "=r"(r[3]) : "r"(addr));
}
__device__ __forceinline__ void cp16(uint32_t dst_smem, const void* src) {
    asm volatile("cp.async.ca.shared.global [%0], [%1], 16;"
                 :: "r"(dst_smem), "l"(src));
}
__device__ __forceinline__ void cpcommit() { asm volatile("cp.async.commit_group;"); }
__device__ __forceinline__ void cpwait1()  { asm volatile("cp.async.wait_group 1;"); }
__device__ __forceinline__ void cpwait0()  { asm volatile("cp.async.wait_group 0;"); }

__device__ __forceinline__ void split_store2(__nv_bfloat16* Chi, __nv_bfloat16* Clo,
                                             size_t off, float v0, float v1) {
    __nv_bfloat16 h0 = __float2bfloat16(v0), h1 = __float2bfloat16(v1);
    __nv_bfloat16 l0 = __float2bfloat16(v0 - __bfloat162float(h0));
    __nv_bfloat16 l1 = __float2bfloat16(v1 - __bfloat162float(h1));
    __nv_bfloat162 H; H.x = h0; H.y = h1;
    __nv_bfloat162 L; L.x = l0; L.y = l1;
    *(__nv_bfloat162*)(Chi + off) = H;
    *(__nv_bfloat162*)(Clo + off) = L;
}

// ---------------------------------------------------------------------------
// K0: split wq into hi/lo bf16
// ---------------------------------------------------------------------------
__global__ __launch_bounds__(256) void wprep_kernel(
    const float* __restrict__ wq, __nv_bfloat16* __restrict__ whi,
    __nv_bfloat16* __restrict__ wlo)
{
    int i = blockIdx.x * 256 + threadIdx.x;
    float v = wq[i];
    __nv_bfloat16 h = __float2bfloat16(v);
    whi[i] = h;
    wlo[i] = __float2bfloat16(v - __bfloat162float(h));
}

// ---------------------------------------------------------------------------
// K1: one CTA per batch element: patchify -> emb GEMM -> +pos -> hi/lo bf16
// ---------------------------------------------------------------------------
__global__ __launch_bounds__(256) void seq_kernel(
    const float* __restrict__ x, const float* __restrict__ proj_w,
    const float* __restrict__ proj_b, const float* __restrict__ cls,
    const float* __restrict__ pos, __nv_bfloat16* __restrict__ shi_,
    __nv_bfloat16* __restrict__ slo_)
{
    __shared__ float ps[NPATCH * 49];
    __shared__ float wt[PFEAT * 66];

    const int b = blockIdx.x;
    const int t = threadIdx.x;
    const int tx = t & 31, ty = t >> 5;
    __nv_bfloat16* shi = shi_ + (size_t)b * SEQL * EMBED;
    __nv_bfloat16* slo = slo_ + (size_t)b * SEQL * EMBED;

    const float* xb = x + (size_t)b * 3 * 32 * 32;
    for (int idx = t; idx < NPATCH * PFEAT; idx += 256) {
        int n = idx / PFEAT, f = idx % PFEAT;
        int c = f >> 4, r4 = (f >> 2) & 3, c4 = f & 3;
        int py = n >> 3, px = n & 7;
        ps[n * 49 + f] = xb[c * 1024 + (py * 4 + r4) * 32 + (px * 4 + c4)];
    }
    for (int e = t; e < EMBED; e += 256) {
        float v = cls[e] + pos[e];
        __nv_bfloat16 h = __float2bfloat16(v);
        shi[e] = h; slo[e] = __float2bfloat16(v - __bfloat162float(h));
    }
    __syncthreads();

    for (int e0 = 0; e0 < EMBED; e0 += 64) {
        {
            int e = t >> 2, fc = (t & 3) * 12;
            const float4* src = (const float4*)(proj_w + (size_t)(e0 + e) * PFEAT + fc);
            #pragma unroll
            for (int j = 0; j < 3; j++) {
                float4 v = src[j];
                wt[(fc + j * 4 + 0) * 66 + e] = v.x;
                wt[(fc + j * 4 + 1) * 66 + e] = v.y;
                wt[(fc + j * 4 + 2) * 66 + e] = v.z;
                wt[(fc + j * 4 + 3) * 66 + e] = v.w;
            }
        }
        __syncthreads();
        int e1 = e0 + 2 * tx;
        float acc[8][2];
        float pb0 = proj_b[e1], pb1 = proj_b[e1 + 1];
        #pragma unroll
        for (int i = 0; i < 8; i++) { acc[i][0] = pb0; acc[i][1] = pb1; }
        #pragma unroll 4
        for (int f = 0; f < PFEAT; f++) {
            float wv0 = wt[f * 66 + 2 * tx], wv1 = wt[f * 66 + 2 * tx + 1];
            #pragma unroll
            for (int i = 0; i < 8; i++) {
                float pv = ps[(ty + 8 * i) * 49 + f];
                acc[i][0] += pv * wv0; acc[i][1] += pv * wv1;
            }
        }
        #pragma unroll
        for (int i = 0; i < 8; i++) {
            int n = ty + 8 * i;
            #pragma unroll
            for (int u = 0; u < 2; u++) {
                float v = acc[i][u] + pos[(1 + n) * EMBED + e1 + u];
                __nv_bfloat16 h = __float2bfloat16(v);
                shi[(1 + n) * EMBED + e1 + u] = h;
                slo[(1 + n) * EMBED + e1 + u] = __float2bfloat16(v - __bfloat162float(h));
            }
        }
        __syncthreads();
    }
}

// ---------------------------------------------------------------------------
// K2: q GEMM via mma.sync + ldmatrix, cp.async double-buffered.
// CTA 128x128, K chunk 32, 8 warps (4m x 2n), warp tile 32x64.
// Output written as bf16 hi/lo pair arrays.
// ---------------------------------------------------------------------------
#define QSTR 40   // smem row stride in bf16 elems (80B: ldmatrix conflict-free)
#define NCH 16    // 512/32 K-chunks

__global__ __launch_bounds__(256, 2) void qgemm_mma_kernel(
    const __nv_bfloat16* __restrict__ Ahi, const __nv_bfloat16* __restrict__ Alo,
    const __nv_bfloat16* __restrict__ Whi, const __nv_bfloat16* __restrict__ Wlo,
    const float* __restrict__ bias,
    __nv_bfloat16* __restrict__ Chi, __nv_bfloat16* __restrict__ Clo)
{
    __shared__ __align__(16) __nv_bfloat16 sAh[2][128 * QSTR];
    __shared__ __align__(16) __nv_bfloat16 sAl[2][128 * QSTR];
    __shared__ __align__(16) __nv_bfloat16 sWh[2][128 * QSTR];
    __shared__ __align__(16) __nv_bfloat16 sWl[2][128 * QSTR];

    const int t = threadIdx.x;
    const int wid = t >> 5, lane = t & 31;
    const int gid = lane >> 2, tig = lane & 3;
    const int wm = wid & 3, wn = wid >> 2;          // 4m x 2n warp grid
    const int m0 = blockIdx.y * 128, n0 = blockIdx.x * 128;

    float acc[2][8][4];
    #pragma unroll
    for (int i = 0; i < 2; i++)
        #pragma unroll
        for (int j = 0; j < 8; j++)
            #pragma unroll
            for (int k = 0; k < 4; k++) acc[i][j][k] = 0.f;

    const int r0 = t >> 2, kq = (t & 3) * 8;
    const uint32_t stg = 128 * QSTR * 2;            // bytes per stage
    const uint32_t rowB = 64 * QSTR * 2;            // 64-row offset in bytes
    const uint32_t bAh = (uint32_t)__cvta_generic_to_shared(&sAh[0][r0 * QSTR + kq]);
    const uint32_t bAl = (uint32_t)__cvta_generic_to_shared(&sAl[0][r0 * QSTR + kq]);
    const uint32_t bWh = (uint32_t)__cvta_generic_to_shared(&sWh[0][r0 * QSTR + kq]);
    const uint32_t bWl = (uint32_t)__cvta_generic_to_shared(&sWl[0][r0 * QSTR + kq]);

    auto issue = [&](int c, int s) {
        size_t ko = (size_t)c * 32 + kq;
        const uint32_t so = s * stg;
        cp16(bAh + so,        Ahi + (size_t)(m0 + r0) * EMBED + ko);
        cp16(bAh + so + rowB, Ahi + (size_t)(m0 + r0 + 64) * EMBED + ko);
        cp16(bAl + so,        Alo + (size_t)(m0 + r0) * EMBED + ko);
        cp16(bAl + so + rowB, Alo + (size_t)(m0 + r0 + 64) * EMBED + ko);
        cp16(bWh + so,        Whi + (size_t)(n0 + r0) * EMBED + ko);
        cp16(bWh + so + rowB, Whi + (size_t)(n0 + r0 + 64) * EMBED + ko);
        cp16(bWl + so,        Wlo + (size_t)(n0 + r0) * EMBED + ko);
        cp16(bWl + so + rowB, Wlo + (size_t)(n0 + r0 + 64) * EMBED + ko);
        cpcommit();
    };

    // ldmatrix lane addressing (element offsets; x2 for bytes)
    const int aoff = (wm * 32 + (lane & 15)) * QSTR + (lane >> 4) * 8;
    const int boffn = wn * 64 + ((lane >> 4) << 3) + (lane & 7);
    const int boffk = ((lane >> 3) & 1) * 8;

    const uint32_t baseAh = (uint32_t)__cvta_generic_to_shared(&sAh[0][0]);
    const uint32_t baseAl = (uint32_t)__cvta_generic_to_shared(&sAl[0][0]);
    const uint32_t baseWh = (uint32_t)__cvta_generic_to_shared(&sWh[0][0]);
    const uint32_t baseWl = (uint32_t)__cvta_generic_to_shared(&sWl[0][0]);

    issue(0, 0);
    for (int c = 0; c < NCH; c++) {
        const int s = c & 1;
        if (c + 1 < NCH) { issue(c + 1, (c + 1) & 1); cpwait1(); }
        else             { cpwait0(); }
        __syncthreads();
        const uint32_t so = s * stg;
        #pragma unroll
        for (int ks = 0; ks < 2; ks++) {
            const int k0 = ks * 16;
            uint32_t ah[2][4], al[2][4];
            #pragma unroll
            for (int mt = 0; mt < 2; mt++) {
                uint32_t ad = (uint32_t)((aoff + mt * 16 * QSTR + k0) * 2);
                ldsm4(ah[mt], baseAh + so + ad);
                ldsm4(al[mt], baseAl + so + ad);
            }
            #pragma unroll
            for (int p = 0; p < 4; p++) {
                uint32_t bh[4], bl[4];
                uint32_t bd = (uint32_t)(((boffn + p * 16) * QSTR + k0 + boffk) * 2);
                ldsm4(bh, baseWh + so + bd);
                ldsm4(bl, baseWl + so + bd);
                #pragma unroll
                for (int mt = 0; mt < 2; mt++) {
                    mma16816(acc[mt][2 * p],     ah[mt], bh);
                    mma16816(acc[mt][2 * p],     ah[mt], bl);
                    mma16816(acc[mt][2 * p],     al[mt], bh);
                    mma16816(acc[mt][2 * p + 1], ah[mt], bh + 2);
                    mma16816(acc[mt][2 * p + 1], ah[mt], bl + 2);
                    mma16816(acc[mt][2 * p + 1], al[mt], bh + 2);
                }
            }
        }
        __syncthreads();
    }

    #pragma unroll
    for (int mt = 0; mt < 2; mt++) {
        int r = m0 + wm * 32 + mt * 16 + gid;
        #pragma unroll
        for (int nt = 0; nt < 8; nt++) {
            int n = n0 + wn * 64 + nt * 8 + tig * 2;
            float b0 = bias[n], b1 = bias[n + 1];
            split_store2(Chi, Clo, (size_t)r * EMBED + n,
                         acc[mt][nt][0] + b0, acc[mt][nt][1] + b1);
            split_store2(Chi, Clo, (size_t)(r + 8) * EMBED + n,
                         acc[mt][nt][2] + b0, acc[mt][nt][3] + b1);
        }
    }
}

// ---------------------------------------------------------------------------
// K3: per (b,h): scores via bf16 mma (64x64 block) + scalar row/col 64,
// col softmax (poly exp), att0 -> ct_pre
// ---------------------------------------------------------------------------
#define ASTR 72   // bf16 row stride (144B: ldmatrix conflict-free)

__global__ __launch_bounds__(128) void attn_kernel(
    const __nv_bfloat16* __restrict__ qhi, const __nv_bfloat16* __restrict__ qlo,
    float* __restrict__ ctpre)
{
    __shared__ __align__(16) __nv_bfloat16 sQh[SEQL * ASTR];
    __shared__ __align__(16) __nv_bfloat16 sQl[SEQL * ASTR];
    __shared__ float sc[SEQL][68];
    __shared__ float w0s[68];

    const int b = blockIdx.y, h = blockIdx.x;
    const int t = threadIdx.x, lane = t & 31, wid = t >> 5;
    const int gid = lane >> 2, tig = lane & 3;
    const __nv_bfloat16* ph = qhi + (size_t)b * SEQL * EMBED + h * HDIM;
    const __nv_bfloat16* pl = qlo + (size_t)b * SEQL * EMBED + h * HDIM;

    for (int idx = t; idx < SEQL * 8; idx += 128) {
        int row = idx >> 3, c8 = (idx & 7) * 8;
        *(uint4*)(sQh + row * ASTR + c8) = *(const uint4*)(ph + (size_t)row * EMBED + c8);
        *(uint4*)(sQl + row * ASTR + c8) = *(const uint4*)(pl + (size_t)row * EMBED + c8);
    }
    __syncthreads();

    // 64x64 score block via mma: warp w -> rows w*16..+15
    const uint32_t baseQh = (uint32_t)__cvta_generic_to_shared(&sQh[0]);
    const uint32_t baseQl = (uint32_t)__cvta_generic_to_shared(&sQl[0]);
    const int m0 = wid * 16;
    const int aoff = (m0 + (lane & 15)) * ASTR + (lane >> 4) * 8;
    const int boffn = ((lane >> 4) << 3) + (lane & 7);
    const int boffk = ((lane >> 3) & 1) * 8;

    float acc[8][4];
    #pragma unroll
    for (int j = 0; j < 8; j++)
        #pragma unroll
        for (int k = 0; k < 4; k++) acc[j][k] = 0.f;

    #pragma unroll
    for (int kc = 0; kc < 4; kc++) {
        const int k0 = kc * 16;
        uint32_t ah[4], al[4];
        ldsm4(ah, baseQh + (uint32_t)((aoff + k0) * 2));
        ldsm4(al, baseQl + (uint32_t)((aoff + k0) * 2));
        #pragma unroll
        for (int p = 0; p < 4; p++) {
            uint32_t bh[4], bl[4];
            uint32_t bd = (uint32_t)(((boffn + p * 16) * ASTR + k0 + boffk) * 2);
            ldsm4(bh, baseQh + bd);
            ldsm4(bl, baseQl + bd);
            mma16816(acc[2 * p],     ah, bh);
            mma16816(acc[2 * p],     ah, bl);
            mma16816(acc[2 * p],     al, bh);
            mma16816(acc[2 * p + 1], ah, bh + 2);
            mma16816(acc[2 * p + 1], ah, bl + 2);
            mma16816(acc[2 * p + 1], al, bh + 2);
        }
    }
    #pragma unroll
    for (int nt = 0; nt < 8; nt++) {
        int rr = m0 + gid, cc = nt * 8 + tig * 2;
        sc[rr][cc]         = acc[nt][0] * 0.125f;
        sc[rr][cc + 1]     = acc[nt][1] * 0.125f;
        sc[rr + 8][cc]     = acc[nt][2] * 0.125f;
        sc[rr + 8][cc + 1] = acc[nt][3] * 0.125f;
    }
    // row 64 (threads 63..127 -> cols 0..64), fp32 reconstructed
    if (t >= 63) {
        int tt = t - 63;
        float a = 0.f;
        #pragma unroll 4
        for (int k = 0; k < HDIM; k++) {
            float q64 = __bfloat162float(sQh[64 * ASTR + k]) +
                        __bfloat162float(sQl[64 * ASTR + k]);
            float qt  = __bfloat162float(sQh[tt * ASTR + k]) +
                        __bfloat162float(sQl[tt * ASTR + k]);
            a += q64 * qt;
        }
        sc[64][tt] = a * 0.125f;
    }
    __syncthreads();
    if (t < 64) sc[t][64] = sc[64][t];   // symmetry
    __syncthreads();

    if (t < SEQL) {
        float m = -1e30f;
        for (int s = 0; s < SEQL; s++) m = fmaxf(m, sc[s][t]);
        float Z = 0.f;
        for (int s = 0; s < SEQL; s++) Z += fexp(sc[s][t] - m);
        w0s[t] = fexp(sc[0][t] - m) / Z;
    }
    __syncthreads();

    if (t < HDIM) {
        float a = 0.f;
        for (int s = 0; s < SEQL; s++) {
            float qv = __bfloat162float(sQh[s * ASTR + t]) +
                       __bfloat162float(sQl[s * ASTR + t]);
            a += w0s[s] * qv;
        }
        ctpre[(size_t)b * EMBED + h * HDIM + t] = a;
    }
}

// ---------------------------------------------------------------------------
// tail GEMM: C[M,N] = A[M,K] @ W[N,K]^T + bias, optional exact GELU
// ---------------------------------------------------------------------------
__global__ __launch_bounds__(256, 2) void gemm_bias_kernel(
    const float* __restrict__ A, const float* __restrict__ W,
    const float* __restrict__ bias, float* __restrict__ C,
    int M, int N, int K, int act)
{
    __shared__ __align__(16) float As[32][68];
    __shared__ __align__(16) float Ws[32][68];
    const int m0 = blockIdx.y * 64, n0 = blockIdx.x * 64;
    const int t = threadIdx.x;
    const int tn = t & 15, tm = t >> 4;
    float acc[4][4] = {};

    for (int k0 = 0; k0 < K; k0 += 32) {
        #pragma unroll
        for (int l = 0; l < 2; l++) {
            int i = t + l * 256;
            int row = i >> 3;
            int kk = (i & 7) * 4;
            float4 v = *(const float4*)(A + (size_t)(m0 + row) * K + k0 + kk);
            As[kk + 0][row] = v.x; As[kk + 1][row] = v.y;
            As[kk + 2][row] = v.z; As[kk + 3][row] = v.w;
            float4 u = *(const float4*)(W + (size_t)(n0 + row) * K + k0 + kk);
            Ws[kk + 0][row] = u.x; Ws[kk + 1][row] = u.y;
            Ws[kk + 2][row] = u.z; Ws[kk + 3][row] = u.w;
        }
        __syncthreads();
        #pragma unroll
        for (int k = 0; k < 32; k++) {
            float4 av = *(const float4*)&As[k][tm * 4];
            float4 wv = *(const float4*)&Ws[k][tn * 4];
            acc[0][0] += av.x * wv.x; acc[0][1] += av.x * wv.y; acc[0][2] += av.x * wv.z; acc[0][3] += av.x * wv.w;
            acc[1][0] += av.y * wv.x; acc[1][1] += av.y * wv.y; acc[1][2] += av.y * wv.z; acc[1][3] += av.y * wv.w;
            acc[2][0] += av.z * wv.x; acc[2][1] += av.z * wv.y; acc[2][2] += av.z * wv.z; acc[2][3] += av.z * wv.w;
            acc[3][0] += av.w * wv.x; acc[3][1] += av.w * wv.y; acc[3][2] += av.w * wv.z; acc[3][3] += av.w * wv.w;
        }
        __syncthreads();
    }
    #pragma unroll
    for (int i = 0; i < 4; i++) {
        #pragma unroll
        for (int j = 0; j < 4; j++) {
            int m = m0 + tm * 4 + i, n = n0 + tn * 4 + j;
            float v = acc[i][j] + bias[n];
            if (act) v = 0.5f * v * (1.f + erff(v * 0.70710678118654752f));
            C[(size_t)m * N + n] = v;
        }
    }
}

// logits: one CTA per batch row, one warp per class
__global__ __launch_bounds__(320) void logits_kernel(
    const float* __restrict__ h, const float* __restrict__ w2,
    const float* __restrict__ b2, float* __restrict__ out)
{
    int b = blockIdx.x;
    int lane = threadIdx.x & 31, w = threadIdx.x >> 5;
    const float* hb = h + (size_t)b * HID;
    float a = 0.f;
    for (int k = lane; k < HID; k += 32) a += hb[k] * w2[(size_t)w * HID + k];
    #pragma unroll
    for (int o = 16; o > 0; o >>= 1) a += __shfl_xor_sync(0xffffffffu, a, o);
    if (lane == 0) out[(size_t)b * NCLS + w] = a + b2[w];
}

extern "C" void kernel_launch(void* const* d_in, const int* in_sizes, int n_in,
                              void* d_out, int out_size)
{
    const float* x      = (const float*)d_in[0];
    const float* proj_w = (const float*)d_in[1];
    const float* proj_b = (const float*)d_in[2];
    const float* cls    = (const float*)d_in[3];
    const float* pos    = (const float*)d_in[4];
    const float* wq     = (const float*)d_in[5];
    const float* bq     = (const float*)d_in[6];
    const float* wo     = (const float*)d_in[7];
    const float* bo     = (const float*)d_in[8];
    const float* w1     = (const float*)d_in[9];
    const float* b1     = (const float*)d_in[10];
    const float* w2     = (const float*)d_in[11];
    const float* b2     = (const float*)d_in[12];
    float* out = (float*)d_out;

    __nv_bfloat16 *p_shi, *p_slo, *p_whi, *p_wlo, *p_qhi, *p_qlo;
    float *p_ctpre, *p_ct, *p_h;
    cudaGetSymbolAddress((void**)&p_shi, g_shi);
    cudaGetSymbolAddress((void**)&p_slo, g_slo);
    cudaGetSymbolAddress((void**)&p_whi, g_whi);
    cudaGetSymbolAddress((void**)&p_wlo, g_wlo);
    cudaGetSymbolAddress((void**)&p_qhi, g_qhi);
    cudaGetSymbolAddress((void**)&p_qlo, g_qlo);
    cudaGetSymbolAddress((void**)&p_ctpre, g_ctpre);
    cudaGetSymbolAddress((void**)&p_ct, g_ct);
    cudaGetSymbolAddress((void**)&p_h, g_h);

    wprep_kernel<<<EMBED * EMBED / 256, 256>>>(wq, p_whi, p_wlo);
    seq_kernel<<<BATCH, 256>>>(x, proj_w, proj_b, cls, pos, p_shi, p_slo);
    qgemm_mma_kernel<<<dim3(EMBED / 128, MTOT / 128), 256>>>(
        p_shi, p_slo, p_whi, p_wlo, bq, p_qhi, p_qlo);
    attn_kernel<<<dim3(HEADS, BATCH), 128>>>(p_qhi, p_qlo, p_ctpre);
    gemm_bias_kernel<<<dim3(EMBED / 64, BATCH / 64), 256>>>(
        p_ctpre, wo, bo, p_ct, BATCH, EMBED, EMBED, 0);
    gemm_bias_kernel<<<dim3(HID / 64, BATCH / 64), 256>>>(
        p_ct, w1, b1, p_h, BATCH, HID, EMBED, 1);
    logits_kernel<<<BATCH, 320>>>(p_h, w2, b2, out);
}